// round 11
// baseline (speedup 1.0000x reference)
#include <cuda_runtime.h>
#include <cuda_bf16.h>
#include <cstdint>

#define SEQ 2048
#define DIM 512
#define QT  32
#define KT  32
#define NT_ 256
#define NIT (SEQ / KT)

#define QS32 260      // word stride of bf16-pair rows (260 % 32 == 4)
#define KBW  8320     // words per hi (or lo) half of one K buffer
#define BUFW 16640    // words per K buffer (hi+lo)
#define SPST 36       // float stride of partial-score rows
#define PS   20       // word stride of P pair rows

// smem word offsets: 3 K buffers at 0, 16640, 33280
#define W_SP  49920   // 4 x (32*36) = 4608
#define W_P0  54528   // 640
#define W_P1  55168   // 640
#define W_M   55808
#define W_L   55840
#define W_SC  55872
#define SMEM_WORDS 55904
#define SMEM_BYTES (SMEM_WORDS * 4)   // 223,616 B

__device__ __forceinline__ uint32_t smem_u32(const void* p) {
    uint32_t a;
    asm("{ .reg .u64 t; cvta.to.shared.u64 t, %1; cvt.u32.u64 %0, t; }" : "=r"(a) : "l"(p));
    return a;
}

// split fp32 pair (x=even-k, y=odd-k) into bf16 hi pair + bf16 residual pair
__device__ __forceinline__ void cvt2(float x, float y, uint32_t& hip, uint32_t& lop) {
    __nv_bfloat16 bx = __float2bfloat16_rn(x);
    __nv_bfloat16 by = __float2bfloat16_rn(y);
    float rx = x - __bfloat162float(bx);
    float ry = y - __bfloat162float(by);
    __nv_bfloat162 h; h.x = bx; h.y = by;
    __nv_bfloat162 l; l.x = __float2bfloat16_rn(rx); l.y = __float2bfloat16_rn(ry);
    hip = *reinterpret_cast<uint32_t*>(&h);
    lop = *reinterpret_cast<uint32_t*>(&l);
}

__device__ __forceinline__ void mma16(float4& d,
                                      uint32_t a0, uint32_t a1, uint32_t a2, uint32_t a3,
                                      uint32_t b0, uint32_t b1) {
    asm volatile(
        "mma.sync.aligned.m16n8k16.row.col.f32.bf16.bf16.f32 "
        "{%0,%1,%2,%3},{%4,%5,%6,%7},{%8,%9},{%0,%1,%2,%3};"
        : "+f"(d.x), "+f"(d.y), "+f"(d.z), "+f"(d.w)
        : "r"(a0), "r"(a1), "r"(a2), "r"(a3), "r"(b0), "r"(b1));
}

__device__ __forceinline__ void ldsm4(uint32_t& r0, uint32_t& r1, uint32_t& r2, uint32_t& r3,
                                      uint32_t a) {
    asm volatile("ldmatrix.sync.aligned.m8n8.x4.shared.b16 {%0,%1,%2,%3}, [%4];"
                 : "=r"(r0), "=r"(r1), "=r"(r2), "=r"(r3) : "r"(a));
}
__device__ __forceinline__ void ldsm4t(uint32_t& r0, uint32_t& r1, uint32_t& r2, uint32_t& r3,
                                       uint32_t a) {
    asm volatile("ldmatrix.sync.aligned.m8n8.x4.trans.shared.b16 {%0,%1,%2,%3}, [%4];"
                 : "=r"(r0), "=r"(r1), "=r"(r2), "=r"(r3) : "r"(a));
}

__global__ void __launch_bounds__(NT_, 1)
attn_flash_v11(const float* __restrict__ enc,
               const float* __restrict__ dec,
               float* __restrict__ out) {
    extern __shared__ uint32_t sm[];
    float* fM  = (float*)(sm + W_M);
    float* fL  = (float*)(sm + W_L);
    float* fSc = (float*)(sm + W_SC);

    const uint32_t sb = smem_u32(sm);
    const int tid  = threadIdx.x;
    const int lane = tid & 31;
    const int wid  = tid >> 5;           // 0..7
    const int g  = lane >> 2;
    const int t  = lane & 3;
    const int l16 = lane & 15;
    const int lhi = lane >> 4;
    const int l8  = lane & 7;
    const int mi  = lane >> 3;

    const int b  = blockIdx.x >> 6;
    const int q0 = (blockIdx.x & 63) * QT;
    const float* decb = dec + ((size_t)b * SEQ + q0) * DIM;
    const float* encb = enc + (size_t)b * SEQ * DIM;

    const int wm = wid >> 2;     // GEMM1 m-half 0..1
    const int wk = wid & 3;      // GEMM1 k-slice 0..3
    const int nb = wid * 64;     // GEMM2 column slice

    // ---- prologue: stage Q (split) into buf1, init stats ----
#pragma unroll
    for (int j = 0; j < 16; j++) {
        int i  = tid + j * NT_;
        int r  = i >> 7;
        int c4 = (i & 127) << 2;
        float4 v = *(const float4*)(decb + r * DIM + c4);
        uint32_t h0, l0, h1, l1;
        cvt2(v.x, v.y, h0, l0);
        cvt2(v.z, v.w, h1, l1);
        uint32_t w = r * QS32 + (c4 >> 1);
        *(uint2*)(sm + BUFW + w) = make_uint2(h0, h1);
        *(uint2*)(sm + BUFW + KBW + w) = make_uint2(l0, l1);
    }
    if (tid < QT) { fM[tid] = -1e30f; fL[tid] = 0.0f; }
    __syncthreads();

    // ---- extract Q fragments into registers (64 regs) ----
    uint32_t qh[8][4], ql[8][4];
    {
        uint32_t aQh = sb + 4u * (BUFW + (wm * 16 + l16) * QS32) + wk * 256 + lhi * 16;
        uint32_t aQl = aQh + 4u * KBW;
#pragma unroll
        for (int s = 0; s < 8; s++) {
            ldsm4(qh[s][0], qh[s][1], qh[s][2], qh[s][3], aQh + s * 32);
            ldsm4(ql[s][0], ql[s][1], ql[s][2], ql[s][3], aQl + s * 32);
        }
    }

    // ---- load K tile 0 into buf0 ----
#pragma unroll
    for (int j = 0; j < 16; j++) {
        int i  = tid + j * NT_;
        int r  = i >> 7;
        int c4 = (i & 127) << 2;
        float4 v = *(const float4*)(encb + (size_t)r * DIM + c4);
        uint32_t h0, l0, h1, l1;
        cvt2(v.x, v.y, h0, l0);
        cvt2(v.z, v.w, h1, l1);
        uint32_t w = r * QS32 + (c4 >> 1);
        *(uint2*)(sm + w) = make_uint2(h0, h1);
        *(uint2*)(sm + KBW + w) = make_uint2(l0, l1);
    }
    __syncthreads();

    float4 o[2][8];
#pragma unroll
    for (int mt = 0; mt < 2; mt++)
#pragma unroll
        for (int nt = 0; nt < 8; nt++) o[mt][nt] = make_float4(0.f, 0.f, 0.f, 0.f);

    const uint32_t aP0 = sb + 4u * (W_P0 + l16 * PS) + lhi * 16;
    const uint32_t aP1 = aP0 + 4u * (W_P1 - W_P0);

    // rescale + GEMM2 reading K buffer at byte base kb2 (P from smem)
    auto do_gemm2 = [&](uint32_t kb2) {
        float sc[4];
#pragma unroll
        for (int j = 0; j < 4; j++) sc[j] = fSc[g + 8 * j];
#pragma unroll
        for (int mt = 0; mt < 2; mt++) {
            float slo = sc[2 * mt], shi = sc[2 * mt + 1];
#pragma unroll
            for (int nt = 0; nt < 8; nt++) {
                o[mt][nt].x *= slo; o[mt][nt].y *= slo;
                o[mt][nt].z *= shi; o[mt][nt].w *= shi;
            }
        }
        uint32_t aE0 = kb2 + 4u * (l16 * QS32) + (uint32_t)nb * 2 + lhi * 16;
        uint32_t aE1 = aE0 + 4u * KBW;
#pragma unroll
        for (int ks = 0; ks < 2; ks++) {
            uint32_t A0[2][4], A1[2][4];
#pragma unroll
            for (int mt = 0; mt < 2; mt++) {
                uint32_t off = (uint32_t)(mt * 16 * PS + ks * 8) * 4;
                ldsm4(A0[mt][0], A0[mt][1], A0[mt][2], A0[mt][3], aP0 + off);
                ldsm4(A1[mt][0], A1[mt][1], A1[mt][2], A1[mt][3], aP1 + off);
            }
            uint32_t eoff = (uint32_t)(ks * 16 * QS32) * 4;
#pragma unroll
            for (int ntp = 0; ntp < 4; ntp++) {
                uint32_t bh0, bh1, bh2, bh3, bl0, bl1, bl2, bl3;
                ldsm4t(bh0, bh1, bh2, bh3, aE0 + eoff + ntp * 32);
                ldsm4t(bl0, bl1, bl2, bl3, aE1 + eoff + ntp * 32);
                int n0 = ntp * 2, n1 = ntp * 2 + 1;
#pragma unroll
                for (int mt = 0; mt < 2; mt++) {
                    mma16(o[mt][n0], A0[mt][0], A0[mt][1], A0[mt][2], A0[mt][3], bl0, bl1);
                    mma16(o[mt][n0], A1[mt][0], A1[mt][1], A1[mt][2], A1[mt][3], bh0, bh1);
                    mma16(o[mt][n0], A0[mt][0], A0[mt][1], A0[mt][2], A0[mt][3], bh0, bh1);
                    mma16(o[mt][n1], A0[mt][0], A0[mt][1], A0[mt][2], A0[mt][3], bl2, bl3);
                    mma16(o[mt][n1], A1[mt][0], A1[mt][1], A1[mt][2], A1[mt][3], bh2, bh3);
                    mma16(o[mt][n1], A0[mt][0], A0[mt][1], A0[mt][2], A0[mt][3], bh2, bh3);
                }
            }
        }
    };

    int cur = 0, prv = 2, nxt = 1;
    for (int it = 0; it < NIT; it++) {
        const bool more = (it + 1 < NIT);
        const uint32_t kb = sb + (uint32_t)cur * (BUFW * 4);
        const float* kgn = encb + (size_t)(it + 1) * KT * DIM;

        // LDG half A (rows 0..15) of next K — latency hides under phase A
        float4 ka[8];
        if (more) {
#pragma unroll
            for (int j = 0; j < 8; j++) {
                int i = tid + j * NT_;
                int r = i >> 7, c4 = (i & 127) << 2;
                ka[j] = *(const float4*)(kgn + (size_t)r * DIM + c4);
            }
        }

        // ---- phase A.1: GEMM1(it) -> Sp ----
        {
            uint32_t aBhA = kb + 4u * (((mi >> 1) * 8 + l8) * QS32) + wk * 256 + (mi & 1) * 16;
            uint32_t aBhB = aBhA + 16u * QS32 * 4;
            uint32_t aBlA = aBhA + 4u * KBW;
            uint32_t aBlB = aBhB + 4u * KBW;
            float4 cH[4], cX[4];
#pragma unroll
            for (int j = 0; j < 4; j++) {
                cH[j] = make_float4(0.f, 0.f, 0.f, 0.f);
                cX[j] = make_float4(0.f, 0.f, 0.f, 0.f);
            }
#pragma unroll
            for (int s = 0; s < 8; s++) {
                uint32_t bh0, bh1, bh2, bh3, bh4, bh5, bh6, bh7;
                uint32_t bl0, bl1, bl2, bl3, bl4, bl5, bl6, bl7;
                ldsm4(bh0, bh1, bh2, bh3, aBhA + s * 32);
                ldsm4(bh4, bh5, bh6, bh7, aBhB + s * 32);
                ldsm4(bl0, bl1, bl2, bl3, aBlA + s * 32);
                ldsm4(bl4, bl5, bl6, bl7, aBlB + s * 32);
                mma16(cH[0], qh[s][0], qh[s][1], qh[s][2], qh[s][3], bh0, bh1);
                mma16(cH[1], qh[s][0], qh[s][1], qh[s][2], qh[s][3], bh2, bh3);
                mma16(cH[2], qh[s][0], qh[s][1], qh[s][2], qh[s][3], bh4, bh5);
                mma16(cH[3], qh[s][0], qh[s][1], qh[s][2], qh[s][3], bh6, bh7);
                mma16(cX[0], qh[s][0], qh[s][1], qh[s][2], qh[s][3], bl0, bl1);
                mma16(cX[1], qh[s][0], qh[s][1], qh[s][2], qh[s][3], bl2, bl3);
                mma16(cX[2], qh[s][0], qh[s][1], qh[s][2], qh[s][3], bl4, bl5);
                mma16(cX[3], qh[s][0], qh[s][1], qh[s][2], qh[s][3], bl6, bl7);
                mma16(cX[0], ql[s][0], ql[s][1], ql[s][2], ql[s][3], bh0, bh1);
                mma16(cX[1], ql[s][0], ql[s][1], ql[s][2], ql[s][3], bh2, bh3);
                mma16(cX[2], ql[s][0], ql[s][1], ql[s][2], ql[s][3], bh4, bh5);
                mma16(cX[3], ql[s][0], ql[s][1], ql[s][2], ql[s][3], bh6, bh7);
            }
            float* sp = (float*)(sm + W_SP + wk * 1152);
            int rr = wm * 16 + g;
#pragma unroll
            for (int j = 0; j < 4; j++) {
                int cc = j * 8 + (t << 1);
                *(float2*)(sp + rr * SPST + cc) =
                    make_float2(cH[j].x + cX[j].x, cH[j].y + cX[j].y);
                *(float2*)(sp + (rr + 8) * SPST + cc) =
                    make_float2(cH[j].z + cX[j].z, cH[j].w + cX[j].w);
            }
        }

        // ---- phase A.2: rescale O + GEMM2(it-1) ----
        if (it > 0) do_gemm2(sb + (uint32_t)prv * (BUFW * 4));
        __syncthreads();

        // ---- phase B: softmax(it) + K(it+1) -> buf[nxt] ----
        {
            uint32_t* kd = sm + (uint32_t)nxt * BUFW;
            float4 kbB[8];
            if (more) {
#pragma unroll
                for (int j = 0; j < 8; j++) {
                    int i = tid + (j + 8) * NT_;
                    int r = i >> 7, c4 = (i & 127) << 2;
                    kbB[j] = *(const float4*)(kgn + (size_t)r * DIM + c4);
                }
            }

            int row = tid >> 3;
            int c4s = (tid & 7) << 2;
            const float* spb = (const float*)(sm + W_SP) + row * SPST + c4s;
            float4 u0 = *(const float4*)(spb);
            float4 u1 = *(const float4*)(spb + 1152);
            float4 u2 = *(const float4*)(spb + 2304);
            float4 u3 = *(const float4*)(spb + 3456);
            float s0 = (u0.x + u1.x) + (u2.x + u3.x);
            float s1 = (u0.y + u1.y) + (u2.y + u3.y);
            float s2 = (u0.z + u1.z) + (u2.z + u3.z);
            float s3 = (u0.w + u1.w) + (u2.w + u3.w);
            float mx = fmaxf(fmaxf(s0, s1), fmaxf(s2, s3));
            mx = fmaxf(mx, __shfl_xor_sync(0xffffffffu, mx, 1));
            mx = fmaxf(mx, __shfl_xor_sync(0xffffffffu, mx, 2));
            mx = fmaxf(mx, __shfl_xor_sync(0xffffffffu, mx, 4));
            float mo = fM[row];
            float mn = fmaxf(mo, mx);
            float p0 = __expf(s0 - mn), p1 = __expf(s1 - mn);
            float p2 = __expf(s2 - mn), p3 = __expf(s3 - mn);
            float su = (p0 + p1) + (p2 + p3);
            su += __shfl_xor_sync(0xffffffffu, su, 1);
            su += __shfl_xor_sync(0xffffffffu, su, 2);
            su += __shfl_xor_sync(0xffffffffu, su, 4);
            if ((tid & 7) == 0) {
                float sc = __expf(mo - mn);
                fSc[row] = sc;
                fM[row]  = mn;
                fL[row]  = fL[row] * sc + su;
            }
            uint32_t h0, l0, h1, l1;
            cvt2(p0, p1, h0, l0);
            cvt2(p2, p3, h1, l1);
            uint32_t w = row * PS + ((tid & 7) << 1);
            *(uint2*)(sm + W_P0 + w) = make_uint2(h0, h1);
            *(uint2*)(sm + W_P1 + w) = make_uint2(l0, l1);

            if (more) {
#pragma unroll
                for (int j = 0; j < 8; j++) {
                    int i = tid + j * NT_;
                    int r = i >> 7, c4 = (i & 127) << 2;
                    uint32_t hh0, ll0, hh1, ll1;
                    cvt2(ka[j].x, ka[j].y, hh0, ll0);
                    cvt2(ka[j].z, ka[j].w, hh1, ll1);
                    uint32_t ww = r * QS32 + (c4 >> 1);
                    *(uint2*)(kd + ww) = make_uint2(hh0, hh1);
                    *(uint2*)(kd + KBW + ww) = make_uint2(ll0, ll1);
                }
#pragma unroll
                for (int j = 0; j < 8; j++) {
                    int i = tid + (j + 8) * NT_;
                    int r = i >> 7, c4 = (i & 127) << 2;
                    uint32_t hh0, ll0, hh1, ll1;
                    cvt2(kbB[j].x, kbB[j].y, hh0, ll0);
                    cvt2(kbB[j].z, kbB[j].w, hh1, ll1);
                    uint32_t ww = r * QS32 + (c4 >> 1);
                    *(uint2*)(kd + ww) = make_uint2(hh0, hh1);
                    *(uint2*)(kd + KBW + ww) = make_uint2(ll0, ll1);
                }
            }
        }
        __syncthreads();

        prv = cur; cur = nxt; nxt = (nxt == 2) ? 0 : nxt + 1;
    }

    // ---- drain: rescale + GEMM2(NIT-1) ----
    do_gemm2(sb + (uint32_t)prv * (BUFW * 4));

    // ---- epilogue: normalize by 1/l and store ----
    {
        float il[4];
#pragma unroll
        for (int j = 0; j < 4; j++) il[j] = 1.0f / fL[g + 8 * j];
        float* ob = out + ((size_t)b * SEQ + q0) * DIM;
#pragma unroll
        for (int mt = 0; mt < 2; mt++) {
            float ilo = il[2 * mt], ihi = il[2 * mt + 1];
            int r = mt * 16 + g;
#pragma unroll
            for (int nt = 0; nt < 8; nt++) {
                int c = nb + nt * 8 + (t << 1);
                float2 v0 = make_float2(o[mt][nt].x * ilo, o[mt][nt].y * ilo);
                float2 v1 = make_float2(o[mt][nt].z * ihi, o[mt][nt].w * ihi);
                *(float2*)(ob + r * DIM + c)       = v0;
                *(float2*)(ob + (r + 8) * DIM + c) = v1;
            }
        }
    }
}

extern "C" void kernel_launch(void* const* d_in, const int* in_sizes, int n_in,
                              void* d_out, int out_size) {
    const float* enc = (const float*)d_in[0];   // enc_outputs [8,2048,512]
    const float* dec = (const float*)d_in[1];   // dec_outputs [8,2048,512]
    float* out = (float*)d_out;                 // [8,2048,512]

    cudaFuncSetAttribute(attn_flash_v11,
                         cudaFuncAttributeMaxDynamicSharedMemorySize, SMEM_BYTES);

    dim3 grid(8 * (SEQ / QT));   // 512 CTAs, 1 per SM
    attn_flash_v11<<<grid, NT_, SMEM_BYTES>>>(enc, dec, out);
}

// round 12
// speedup vs baseline: 1.2614x; 1.2614x over previous
#include <cuda_runtime.h>
#include <cuda_bf16.h>
#include <cstdint>

#define SEQ 2048
#define DIM 512
#define NB  8

// 128 MB scratch for S / P
__device__ float g_S[(size_t)NB * SEQ * SEQ];

// ---------------- helpers (all numerically proven in rounds 4-11) ----------------
__device__ __forceinline__ uint32_t smem_u32(const void* p) {
    uint32_t a;
    asm("{ .reg .u64 t; cvta.to.shared.u64 t, %1; cvt.u32.u64 %0, t; }" : "=r"(a) : "l"(p));
    return a;
}

// split fp32 pair (x=even-k, y=odd-k) into bf16 hi pair + bf16 residual pair
__device__ __forceinline__ void cvt2(float x, float y, uint32_t& hip, uint32_t& lop) {
    __nv_bfloat16 bx = __float2bfloat16_rn(x);
    __nv_bfloat16 by = __float2bfloat16_rn(y);
    float rx = x - __bfloat162float(bx);
    float ry = y - __bfloat162float(by);
    __nv_bfloat162 h; h.x = bx; h.y = by;
    __nv_bfloat162 l; l.x = __float2bfloat16_rn(rx); l.y = __float2bfloat16_rn(ry);
    hip = *reinterpret_cast<uint32_t*>(&h);
    lop = *reinterpret_cast<uint32_t*>(&l);
}

__device__ __forceinline__ void mma16(float4& d,
                                      uint32_t a0, uint32_t a1, uint32_t a2, uint32_t a3,
                                      uint32_t b0, uint32_t b1) {
    asm volatile(
        "mma.sync.aligned.m16n8k16.row.col.f32.bf16.bf16.f32 "
        "{%0,%1,%2,%3},{%4,%5,%6,%7},{%8,%9},{%0,%1,%2,%3};"
        : "+f"(d.x), "+f"(d.y), "+f"(d.z), "+f"(d.w)
        : "r"(a0), "r"(a1), "r"(a2), "r"(a3), "r"(b0), "r"(b1));
}

__device__ __forceinline__ void ldsm4(uint32_t& r0, uint32_t& r1, uint32_t& r2, uint32_t& r3,
                                      uint32_t a) {
    asm volatile("ldmatrix.sync.aligned.m8n8.x4.shared.b16 {%0,%1,%2,%3}, [%4];"
                 : "=r"(r0), "=r"(r1), "=r"(r2), "=r"(r3) : "r"(a));
}
__device__ __forceinline__ void ldsm4t(uint32_t& r0, uint32_t& r1, uint32_t& r2, uint32_t& r3,
                                       uint32_t a) {
    asm volatile("ldmatrix.sync.aligned.m8n8.x4.trans.shared.b16 {%0,%1,%2,%3}, [%4];"
                 : "=r"(r0), "=r"(r1), "=r"(r2), "=r"(r3) : "r"(a));
}

// pair-row layout: 64 k-floats per row = 32 bf16x2 pairs + 4 pad words
#define RS 36     // words per row (4*RS = 144 B); banks 4r%32 distinct for r0..7

// ================= GEMM1: S[2048,2048] = dec @ enc^T (3-term split-bf16) =================
#define G1_ATW  (128 * RS)        // 4608 words per 128-row matrix
#define G1_STGW (4 * G1_ATW)      // Ah, Al, Bh, Bl per stage
#define G1_SMEM (2 * G1_STGW * 4) // 147,456 B

__global__ void __launch_bounds__(256)
gemm1_kernel(const float* __restrict__ dec, const float* __restrict__ enc,
             float* __restrict__ S) {
    extern __shared__ uint32_t sm[];
    const uint32_t sb = smem_u32(sm);
    const int tid = threadIdx.x, lane = tid & 31, wid = tid >> 5;
    const int l16 = lane & 15, lhi = lane >> 4, l8 = lane & 7, mi = lane >> 3;
    const int g = lane >> 2, t = lane & 3;
    const int wm = wid >> 2, wn = wid & 3;       // warp tile 64m x 32n
    const int n0 = blockIdx.x * 128, m0 = blockIdx.y * 128, bz = blockIdx.z;

    const float* Ab = dec + ((size_t)bz * SEQ + m0) * DIM;
    const float* Bb = enc + ((size_t)bz * SEQ + n0) * DIM;
    float* Cb = S + (size_t)bz * SEQ * SEQ + (size_t)m0 * SEQ + n0;

    float4 acc[4][4];
#pragma unroll
    for (int a = 0; a < 4; a++)
#pragma unroll
        for (int b = 0; b < 4; b++) acc[a][b] = make_float4(0.f, 0.f, 0.f, 0.f);

    // ---- prologue: load chunk 0 into stage 0 ----
#pragma unroll
    for (int i = 0; i < 8; i++) {
        int idx = tid + i * 256;
        int r = idx >> 4, c4 = (idx & 15) << 2;
        uint32_t w = r * RS + (c4 >> 1);
        float4 v = *(const float4*)(Ab + (size_t)r * DIM + c4);
        uint32_t h0, l0, h1, l1;
        cvt2(v.x, v.y, h0, l0); cvt2(v.z, v.w, h1, l1);
        *(uint2*)(sm + w) = make_uint2(h0, h1);
        *(uint2*)(sm + G1_ATW + w) = make_uint2(l0, l1);
        v = *(const float4*)(Bb + (size_t)r * DIM + c4);
        cvt2(v.x, v.y, h0, l0); cvt2(v.z, v.w, h1, l1);
        *(uint2*)(sm + 2 * G1_ATW + w) = make_uint2(h0, h1);
        *(uint2*)(sm + 3 * G1_ATW + w) = make_uint2(l0, l1);
    }
    __syncthreads();

    for (int c = 0; c < 8; c++) {
        const int s = c & 1;
        // stage next chunk's LDGs into registers (latency hidden by mma below)
        float4 va[8], vb[8];
        if (c < 7) {
            const float* ap = Ab + (c + 1) * 64;
            const float* bp = Bb + (c + 1) * 64;
#pragma unroll
            for (int i = 0; i < 8; i++) {
                int idx = tid + i * 256;
                int r = idx >> 4, c4 = (idx & 15) << 2;
                va[i] = *(const float4*)(ap + (size_t)r * DIM + c4);
                vb[i] = *(const float4*)(bp + (size_t)r * DIM + c4);
            }
        }
        // ---- mma over stage s ----
        {
            const uint32_t base = sb + (uint32_t)s * (G1_STGW * 4);
            const uint32_t aA  = base + (uint32_t)(wm * 64 + l16) * 144 + lhi * 16;
            const uint32_t aAl = aA + G1_ATW * 4;
            const uint32_t aB  = base + 2u * G1_ATW * 4 +
                                 (uint32_t)(wn * 32 + (mi >> 1) * 8 + l8) * 144 + (mi & 1) * 16;
            const uint32_t aBl = aB + G1_ATW * 4;
#pragma unroll
            for (int st = 0; st < 4; st++) {
                uint32_t ah[4][4], al[4][4];
#pragma unroll
                for (int mt = 0; mt < 4; mt++) {
                    ldsm4(ah[mt][0], ah[mt][1], ah[mt][2], ah[mt][3], aA + mt * 2304 + st * 32);
                    ldsm4(al[mt][0], al[mt][1], al[mt][2], al[mt][3], aAl + mt * 2304 + st * 32);
                }
                uint32_t bh[8], bl[8];
                ldsm4(bh[0], bh[1], bh[2], bh[3], aB + st * 32);
                ldsm4(bh[4], bh[5], bh[6], bh[7], aB + 16 * 144 + st * 32);
                ldsm4(bl[0], bl[1], bl[2], bl[3], aBl + st * 32);
                ldsm4(bl[4], bl[5], bl[6], bl[7], aBl + 16 * 144 + st * 32);
#pragma unroll
                for (int mt = 0; mt < 4; mt++)
#pragma unroll
                    for (int np = 0; np < 4; np++) {
                        mma16(acc[mt][np], ah[mt][0], ah[mt][1], ah[mt][2], ah[mt][3],
                              bl[np * 2], bl[np * 2 + 1]);
                        mma16(acc[mt][np], al[mt][0], al[mt][1], al[mt][2], al[mt][3],
                              bh[np * 2], bh[np * 2 + 1]);
                        mma16(acc[mt][np], ah[mt][0], ah[mt][1], ah[mt][2], ah[mt][3],
                              bh[np * 2], bh[np * 2 + 1]);
                    }
            }
        }
        // ---- STS next chunk into stage s^1 ----
        if (c < 7) {
            uint32_t* stg = sm + (uint32_t)(s ^ 1) * G1_STGW;
#pragma unroll
            for (int i = 0; i < 8; i++) {
                int idx = tid + i * 256;
                int r = idx >> 4, c4 = (idx & 15) << 2;
                uint32_t w = r * RS + (c4 >> 1);
                uint32_t h0, l0, h1, l1;
                cvt2(va[i].x, va[i].y, h0, l0); cvt2(va[i].z, va[i].w, h1, l1);
                *(uint2*)(stg + w) = make_uint2(h0, h1);
                *(uint2*)(stg + G1_ATW + w) = make_uint2(l0, l1);
                cvt2(vb[i].x, vb[i].y, h0, l0); cvt2(vb[i].z, vb[i].w, h1, l1);
                *(uint2*)(stg + 2 * G1_ATW + w) = make_uint2(h0, h1);
                *(uint2*)(stg + 3 * G1_ATW + w) = make_uint2(l0, l1);
            }
        }
        __syncthreads();
    }

    // ---- epilogue ----
#pragma unroll
    for (int mt = 0; mt < 4; mt++) {
        int r = wm * 64 + mt * 16 + g;
#pragma unroll
        for (int np = 0; np < 4; np++) {
            int cc = wn * 32 + np * 8 + (t << 1);
            *(float2*)(Cb + (size_t)r * SEQ + cc)       = make_float2(acc[mt][np].x, acc[mt][np].y);
            *(float2*)(Cb + (size_t)(r + 8) * SEQ + cc) = make_float2(acc[mt][np].z, acc[mt][np].w);
        }
    }
}

// ================= softmax over rows of S (in place) =================
__global__ void __launch_bounds__(256)
softmax_kernel(float* __restrict__ S) {
    float* p = S + (size_t)blockIdx.x * SEQ;
    __shared__ float red[8];
    const int tid = threadIdx.x, wid = tid >> 5, lane = tid & 31;

    float4 v0 = *(float4*)(p + tid * 4);
    float4 v1 = *(float4*)(p + 1024 + tid * 4);

    float m = fmaxf(fmaxf(fmaxf(v0.x, v0.y), fmaxf(v0.z, v0.w)),
                    fmaxf(fmaxf(v1.x, v1.y), fmaxf(v1.z, v1.w)));
#pragma unroll
    for (int o = 16; o; o >>= 1) m = fmaxf(m, __shfl_xor_sync(0xffffffffu, m, o));
    if (!lane) red[wid] = m;
    __syncthreads();
    if (tid < 32) {
        float x = (lane < 8) ? red[lane] : -1e30f;
#pragma unroll
        for (int o = 4; o; o >>= 1) x = fmaxf(x, __shfl_xor_sync(0xffffffffu, x, o));
        if (!lane) red[0] = x;
    }
    __syncthreads();
    float M = red[0];
    __syncthreads();

    v0.x = __expf(v0.x - M); v0.y = __expf(v0.y - M);
    v0.z = __expf(v0.z - M); v0.w = __expf(v0.w - M);
    v1.x = __expf(v1.x - M); v1.y = __expf(v1.y - M);
    v1.z = __expf(v1.z - M); v1.w = __expf(v1.w - M);

    float su = (v0.x + v0.y) + (v0.z + v0.w) + (v1.x + v1.y) + (v1.z + v1.w);
#pragma unroll
    for (int o = 16; o; o >>= 1) su += __shfl_xor_sync(0xffffffffu, su, o);
    if (!lane) red[wid] = su;
    __syncthreads();
    if (tid < 32) {
        float x = (lane < 8) ? red[lane] : 0.0f;
#pragma unroll
        for (int o = 4; o; o >>= 1) x += __shfl_xor_sync(0xffffffffu, x, o);
        if (!lane) red[0] = x;
    }
    __syncthreads();
    float inv = 1.0f / red[0];

    v0.x *= inv; v0.y *= inv; v0.z *= inv; v0.w *= inv;
    v1.x *= inv; v1.y *= inv; v1.z *= inv; v1.w *= inv;
    *(float4*)(p + tid * 4) = v0;
    *(float4*)(p + 1024 + tid * 4) = v1;
}

// ================= GEMM2: out[2048,512] = P @ enc (3-term split-bf16, TransB via ldsm4t) ======
#define G2_PATW (128 * RS)                 // 4608 words (P hi or lo)
#define G2_EATW (64 * RS)                  // 2304 words (E hi or lo)
#define G2_STGW (2 * G2_PATW + 2 * G2_EATW)  // 13824 words per stage
#define G2_SMEM (2 * G2_STGW * 4)          // 110,592 B

__global__ void __launch_bounds__(256)
gemm2_kernel(const float* __restrict__ S, const float* __restrict__ enc,
             float* __restrict__ out) {
    extern __shared__ uint32_t sm[];
    const uint32_t sb = smem_u32(sm);
    const int tid = threadIdx.x, lane = tid & 31, wid = tid >> 5;
    const int l16 = lane & 15, lhi = lane >> 4;
    const int g = lane >> 2, t = lane & 3;
    const int wm = wid >> 1, wd = wid & 1;       // warp tile 32m x 32d
    const int d0 = blockIdx.x * 64, m0 = blockIdx.y * 128, bz = blockIdx.z;

    const float* Pb = S + (size_t)bz * SEQ * SEQ + (size_t)m0 * SEQ;
    const float* Eb = enc + (size_t)bz * SEQ * DIM + d0;
    float* Ob = out + ((size_t)bz * SEQ + m0) * DIM + d0;

    float4 acc[2][4];
#pragma unroll
    for (int a = 0; a < 2; a++)
#pragma unroll
        for (int b = 0; b < 4; b++) acc[a][b] = make_float4(0.f, 0.f, 0.f, 0.f);

    // ---- prologue: load chunk 0 into stage 0 ----
#pragma unroll
    for (int i = 0; i < 8; i++) {     // P: 128 rows x 64 k
        int idx = tid + i * 256;
        int r = idx >> 4, c4 = (idx & 15) << 2;
        uint32_t w = r * RS + (c4 >> 1);
        float4 v = *(const float4*)(Pb + (size_t)r * SEQ + c4);
        uint32_t h0, l0, h1, l1;
        cvt2(v.x, v.y, h0, l0); cvt2(v.z, v.w, h1, l1);
        *(uint2*)(sm + w) = make_uint2(h0, h1);
        *(uint2*)(sm + G2_PATW + w) = make_uint2(l0, l1);
    }
#pragma unroll
    for (int i = 0; i < 4; i++) {     // E: 64 k-rows x 64 d
        int idx = tid + i * 256;
        int r = idx >> 4, c4 = (idx & 15) << 2;
        uint32_t w = r * RS + (c4 >> 1);
        float4 v = *(const float4*)(Eb + (size_t)r * DIM + c4);
        uint32_t h0, l0, h1, l1;
        cvt2(v.x, v.y, h0, l0); cvt2(v.z, v.w, h1, l1);
        *(uint2*)(sm + 2 * G2_PATW + w) = make_uint2(h0, h1);
        *(uint2*)(sm + 2 * G2_PATW + G2_EATW + w) = make_uint2(l0, l1);
    }
    __syncthreads();

    for (int c = 0; c < 32; c++) {
        const int s = c & 1;
        float4 vp[8], ve[4];
        if (c < 31) {
            const float* pp = Pb + (c + 1) * 64;
            const float* ep = Eb + (size_t)(c + 1) * 64 * DIM;
#pragma unroll
            for (int i = 0; i < 8; i++) {
                int idx = tid + i * 256;
                int r = idx >> 4, c4 = (idx & 15) << 2;
                vp[i] = *(const float4*)(pp + (size_t)r * SEQ + c4);
            }
#pragma unroll
            for (int i = 0; i < 4; i++) {
                int idx = tid + i * 256;
                int r = idx >> 4, c4 = (idx & 15) << 2;
                ve[i] = *(const float4*)(ep + (size_t)r * DIM + c4);
            }
        }
        // ---- mma over stage s ----
        {
            const uint32_t base = sb + (uint32_t)s * (G2_STGW * 4);
            const uint32_t aP  = base + (uint32_t)(wm * 32 + l16) * 144 + lhi * 16;
            const uint32_t aPl = aP + G2_PATW * 4;
            const uint32_t aE  = base + 2u * G2_PATW * 4 + (uint32_t)l16 * 144 + wd * 64 + lhi * 16;
            const uint32_t aEl = aE + G2_EATW * 4;
#pragma unroll
            for (int st = 0; st < 4; st++) {
                uint32_t ph[2][4], pl[2][4];
#pragma unroll
                for (int mt = 0; mt < 2; mt++) {
                    ldsm4(ph[mt][0], ph[mt][1], ph[mt][2], ph[mt][3], aP + mt * 2304 + st * 32);
                    ldsm4(pl[mt][0], pl[mt][1], pl[mt][2], pl[mt][3], aPl + mt * 2304 + st * 32);
                }
                uint32_t eh[8], el[8];
                ldsm4t(eh[0], eh[1], eh[2], eh[3], aE + st * 2304);
                ldsm4t(eh[4], eh[5], eh[6], eh[7], aE + st * 2304 + 32);
                ldsm4t(el[0], el[1], el[2], el[3], aEl + st * 2304);
                ldsm4t(el[4], el[5], el[6], el[7], aEl + st * 2304 + 32);
#pragma unroll
                for (int mt = 0; mt < 2; mt++)
#pragma unroll
                    for (int np = 0; np < 4; np++) {
                        mma16(acc[mt][np], ph[mt][0], ph[mt][1], ph[mt][2], ph[mt][3],
                              el[np * 2], el[np * 2 + 1]);
                        mma16(acc[mt][np], pl[mt][0], pl[mt][1], pl[mt][2], pl[mt][3],
                              eh[np * 2], eh[np * 2 + 1]);
                        mma16(acc[mt][np], ph[mt][0], ph[mt][1], ph[mt][2], ph[mt][3],
                              eh[np * 2], eh[np * 2 + 1]);
                    }
            }
        }
        // ---- STS next chunk into stage s^1 ----
        if (c < 31) {
            uint32_t* stg = sm + (uint32_t)(s ^ 1) * G2_STGW;
#pragma unroll
            for (int i = 0; i < 8; i++) {
                int idx = tid + i * 256;
                int r = idx >> 4, c4 = (idx & 15) << 2;
                uint32_t w = r * RS + (c4 >> 1);
                uint32_t h0, l0, h1, l1;
                cvt2(vp[i].x, vp[i].y, h0, l0); cvt2(vp[i].z, vp[i].w, h1, l1);
                *(uint2*)(stg + w) = make_uint2(h0, h1);
                *(uint2*)(stg + G2_PATW + w) = make_uint2(l0, l1);
            }
#pragma unroll
            for (int i = 0; i < 4; i++) {
                int idx = tid + i * 256;
                int r = idx >> 4, c4 = (idx & 15) << 2;
                uint32_t w = r * RS + (c4 >> 1);
                uint32_t h0, l0, h1, l1;
                cvt2(ve[i].x, ve[i].y, h0, l0); cvt2(ve[i].z, ve[i].w, h1, l1);
                *(uint2*)(stg + 2 * G2_PATW + w) = make_uint2(h0, h1);
                *(uint2*)(stg + 2 * G2_PATW + G2_EATW + w) = make_uint2(l0, l1);
            }
        }
        __syncthreads();
    }

    // ---- epilogue ----
#pragma unroll
    for (int mt = 0; mt < 2; mt++) {
        int r = wm * 32 + mt * 16 + g;
#pragma unroll
        for (int np = 0; np < 4; np++) {
            int cc = wd * 32 + np * 8 + (t << 1);
            *(float2*)(Ob + (size_t)r * DIM + cc)       = make_float2(acc[mt][np].x, acc[mt][np].y);
            *(float2*)(Ob + (size_t)(r + 8) * DIM + cc) = make_float2(acc[mt][np].z, acc[mt][np].w);
        }
    }
}

// ================= launch =================
extern "C" void kernel_launch(void* const* d_in, const int* in_sizes, int n_in,
                              void* d_out, int out_size) {
    const float* enc = (const float*)d_in[0];   // enc_outputs [8,2048,512]
    const float* dec = (const float*)d_in[1];   // dec_outputs [8,2048,512]
    float* out = (float*)d_out;                 // [8,2048,512]

    float* S = nullptr;
    cudaGetSymbolAddress((void**)&S, g_S);

    cudaFuncSetAttribute(gemm1_kernel, cudaFuncAttributeMaxDynamicSharedMemorySize, G1_SMEM);
    cudaFuncSetAttribute(gemm2_kernel, cudaFuncAttributeMaxDynamicSharedMemorySize, G2_SMEM);

    gemm1_kernel<<<dim3(16, 16, NB), 256, G1_SMEM>>>(dec, enc, S);
    softmax_kernel<<<NB * SEQ, 256>>>(S);
    gemm2_kernel<<<dim3(8, 16, NB), 256, G2_SMEM>>>(S, enc, out);
}

// round 13
// speedup vs baseline: 1.3935x; 1.1048x over previous
#include <cuda_runtime.h>
#include <cuda_bf16.h>
#include <cstdint>

#define SEQ 2048
#define DIM 512
#define NB  8

// device scratch: S fp32 + split-bf16 operand arrays (pair-packed: even k in low half)
__device__ float    g_S [(size_t)NB * SEQ * SEQ];            // 128 MB
__device__ uint32_t g_eh[(size_t)NB * SEQ * (DIM / 2)];      // enc hi   16 MB
__device__ uint32_t g_el[(size_t)NB * SEQ * (DIM / 2)];      // enc lo
__device__ uint32_t g_dh[(size_t)NB * SEQ * (DIM / 2)];      // dec hi
__device__ uint32_t g_dl[(size_t)NB * SEQ * (DIM / 2)];      // dec lo
__device__ uint32_t g_ph[(size_t)NB * SEQ * (SEQ / 2)];      // P hi     64 MB
__device__ uint32_t g_pl[(size_t)NB * SEQ * (SEQ / 2)];      // P lo

// ---------------- helpers ----------------
__device__ __forceinline__ uint32_t smem_u32(const void* p) {
    uint32_t a;
    asm("{ .reg .u64 t; cvta.to.shared.u64 t, %1; cvt.u32.u64 %0, t; }" : "=r"(a) : "l"(p));
    return a;
}

// split fp32 pair (x=even-k, y=odd-k) into bf16 hi pair + bf16 residual pair
__device__ __forceinline__ void cvt2(float x, float y, uint32_t& hip, uint32_t& lop) {
    __nv_bfloat16 bx = __float2bfloat16_rn(x);
    __nv_bfloat16 by = __float2bfloat16_rn(y);
    float rx = x - __bfloat162float(bx);
    float ry = y - __bfloat162float(by);
    __nv_bfloat162 h; h.x = bx; h.y = by;
    __nv_bfloat162 l; l.x = __float2bfloat16_rn(rx); l.y = __float2bfloat16_rn(ry);
    hip = *reinterpret_cast<uint32_t*>(&h);
    lop = *reinterpret_cast<uint32_t*>(&l);
}

__device__ __forceinline__ void mma16(float4& d,
                                      uint32_t a0, uint32_t a1, uint32_t a2, uint32_t a3,
                                      uint32_t b0, uint32_t b1) {
    asm volatile(
        "mma.sync.aligned.m16n8k16.row.col.f32.bf16.bf16.f32 "
        "{%0,%1,%2,%3},{%4,%5,%6,%7},{%8,%9},{%0,%1,%2,%3};"
        : "+f"(d.x), "+f"(d.y), "+f"(d.z), "+f"(d.w)
        : "r"(a0), "r"(a1), "r"(a2), "r"(a3), "r"(b0), "r"(b1));
}

__device__ __forceinline__ void ldsm4(uint32_t& r0, uint32_t& r1, uint32_t& r2, uint32_t& r3,
                                      uint32_t a) {
    asm volatile("ldmatrix.sync.aligned.m8n8.x4.shared.b16 {%0,%1,%2,%3}, [%4];"
                 : "=r"(r0), "=r"(r1), "=r"(r2), "=r"(r3) : "r"(a));
}
__device__ __forceinline__ void ldsm4t(uint32_t& r0, uint32_t& r1, uint32_t& r2, uint32_t& r3,
                                       uint32_t a) {
    asm volatile("ldmatrix.sync.aligned.m8n8.x4.trans.shared.b16 {%0,%1,%2,%3}, [%4];"
                 : "=r"(r0), "=r"(r1), "=r"(r2), "=r"(r3) : "r"(a));
}

#define RS 36     // words per smem row (32 pair-words + 4 pad)

// ================= split kernel: fp32 -> pair-packed bf16 hi/lo =================
// grid (4096, 2): y=0 -> enc, y=1 -> dec.  Each thread: 8 floats = 4 pairs.
__global__ void __launch_bounds__(256)
split_kernel(const float* __restrict__ enc, const float* __restrict__ dec) {
    const size_t t = (size_t)blockIdx.x * 256 + threadIdx.x;    // 4-pair group index
    const float* src = blockIdx.y ? dec : enc;
    uint32_t* dh = blockIdx.y ? g_dh : g_eh;
    uint32_t* dl = blockIdx.y ? g_dl : g_el;
    float4 v0 = *(const float4*)(src + t * 8);
    float4 v1 = *(const float4*)(src + t * 8 + 4);
    uint4 h, l;
    cvt2(v0.x, v0.y, h.x, l.x);
    cvt2(v0.z, v0.w, h.y, l.y);
    cvt2(v1.x, v1.y, h.z, l.z);
    cvt2(v1.z, v1.w, h.w, l.w);
    *(uint4*)(dh + t * 4) = h;
    *(uint4*)(dl + t * 4) = l;
}

// ================= GEMM1: S = dec @ enc^T (3-term split-bf16) =================
#define G1_ATW  (128 * RS)
#define G1_STGW (4 * G1_ATW)
#define G1_SMEM (2 * G1_STGW * 4)   // 147,456 B

__global__ void __launch_bounds__(256)
gemm1_kernel(float* __restrict__ S) {
    extern __shared__ uint32_t sm[];
    const uint32_t sb = smem_u32(sm);
    const int tid = threadIdx.x, lane = tid & 31, wid = tid >> 5;
    const int l16 = lane & 15, lhi = lane >> 4, l8 = lane & 7, mi = lane >> 3;
    const int g = lane >> 2, t = lane & 3;
    const int wm = wid >> 2, wn = wid & 3;
    const int n0 = blockIdx.x * 128, m0 = blockIdx.y * 128, bz = blockIdx.z;

    const uint32_t* Ah = g_dh + ((size_t)bz * SEQ + m0) * 256;
    const uint32_t* Al = g_dl + ((size_t)bz * SEQ + m0) * 256;
    const uint32_t* Bh = g_eh + ((size_t)bz * SEQ + n0) * 256;
    const uint32_t* Bl = g_el + ((size_t)bz * SEQ + n0) * 256;
    float* Cb = S + (size_t)bz * SEQ * SEQ + (size_t)m0 * SEQ + n0;

    float4 acc[4][4];
#pragma unroll
    for (int a = 0; a < 4; a++)
#pragma unroll
        for (int b = 0; b < 4; b++) acc[a][b] = make_float4(0.f, 0.f, 0.f, 0.f);

    // prologue: chunk 0 -> stage 0  (pure LDG->STS)
#pragma unroll
    for (int i = 0; i < 4; i++) {
        int idx = tid + i * 256;
        int r = idx >> 3, u = idx & 7;
        uint32_t w = r * RS + u * 4;
        size_t ga = (size_t)r * 256 + u * 4;
        *(uint4*)(sm + w)              = *(const uint4*)(Ah + ga);
        *(uint4*)(sm + G1_ATW + w)     = *(const uint4*)(Al + ga);
        *(uint4*)(sm + 2 * G1_ATW + w) = *(const uint4*)(Bh + ga);
        *(uint4*)(sm + 3 * G1_ATW + w) = *(const uint4*)(Bl + ga);
    }
    __syncthreads();

    for (int c = 0; c < 8; c++) {
        const int s = c & 1;
        uint4 va[4], vl[4], vb[4], vm[4];
        if (c < 7) {
            int co = (c + 1) * 32;
#pragma unroll
            for (int i = 0; i < 4; i++) {
                int idx = tid + i * 256;
                int r = idx >> 3, u = idx & 7;
                size_t ga = (size_t)r * 256 + co + u * 4;
                va[i] = *(const uint4*)(Ah + ga);
                vl[i] = *(const uint4*)(Al + ga);
                vb[i] = *(const uint4*)(Bh + ga);
                vm[i] = *(const uint4*)(Bl + ga);
            }
        }
        // ---- mma over stage s (verbatim v12) ----
        {
            const uint32_t base = sb + (uint32_t)s * (G1_STGW * 4);
            const uint32_t aA  = base + (uint32_t)(wm * 64 + l16) * 144 + lhi * 16;
            const uint32_t aAl = aA + G1_ATW * 4;
            const uint32_t aB  = base + 2u * G1_ATW * 4 +
                                 (uint32_t)(wn * 32 + (mi >> 1) * 8 + l8) * 144 + (mi & 1) * 16;
            const uint32_t aBl = aB + G1_ATW * 4;
#pragma unroll
            for (int st = 0; st < 4; st++) {
                uint32_t ah[4][4], al[4][4];
#pragma unroll
                for (int mt = 0; mt < 4; mt++) {
                    ldsm4(ah[mt][0], ah[mt][1], ah[mt][2], ah[mt][3], aA + mt * 2304 + st * 32);
                    ldsm4(al[mt][0], al[mt][1], al[mt][2], al[mt][3], aAl + mt * 2304 + st * 32);
                }
                uint32_t bh[8], bl[8];
                ldsm4(bh[0], bh[1], bh[2], bh[3], aB + st * 32);
                ldsm4(bh[4], bh[5], bh[6], bh[7], aB + 16 * 144 + st * 32);
                ldsm4(bl[0], bl[1], bl[2], bl[3], aBl + st * 32);
                ldsm4(bl[4], bl[5], bl[6], bl[7], aBl + 16 * 144 + st * 32);
#pragma unroll
                for (int mt = 0; mt < 4; mt++)
#pragma unroll
                    for (int np = 0; np < 4; np++) {
                        mma16(acc[mt][np], ah[mt][0], ah[mt][1], ah[mt][2], ah[mt][3],
                              bl[np * 2], bl[np * 2 + 1]);
                        mma16(acc[mt][np], al[mt][0], al[mt][1], al[mt][2], al[mt][3],
                              bh[np * 2], bh[np * 2 + 1]);
                        mma16(acc[mt][np], ah[mt][0], ah[mt][1], ah[mt][2], ah[mt][3],
                              bh[np * 2], bh[np * 2 + 1]);
                    }
            }
        }
        // ---- STS next chunk ----
        if (c < 7) {
            uint32_t* stg = sm + (uint32_t)(s ^ 1) * G1_STGW;
#pragma unroll
            for (int i = 0; i < 4; i++) {
                int idx = tid + i * 256;
                int r = idx >> 3, u = idx & 7;
                uint32_t w = r * RS + u * 4;
                *(uint4*)(stg + w)              = va[i];
                *(uint4*)(stg + G1_ATW + w)     = vl[i];
                *(uint4*)(stg + 2 * G1_ATW + w) = vb[i];
                *(uint4*)(stg + 3 * G1_ATW + w) = vm[i];
            }
        }
        __syncthreads();
    }

#pragma unroll
    for (int mt = 0; mt < 4; mt++) {
        int r = wm * 64 + mt * 16 + g;
#pragma unroll
        for (int np = 0; np < 4; np++) {
            int cc = wn * 32 + np * 8 + (t << 1);
            *(float2*)(Cb + (size_t)r * SEQ + cc)       = make_float2(acc[mt][np].x, acc[mt][np].y);
            *(float2*)(Cb + (size_t)(r + 8) * SEQ + cc) = make_float2(acc[mt][np].z, acc[mt][np].w);
        }
    }
}

// ================= softmax: S row -> pair-packed split-bf16 P =================
__global__ void __launch_bounds__(256)
softmax_kernel() {
    const float* p = g_S + (size_t)blockIdx.x * SEQ;
    uint32_t* ph = g_ph + (size_t)blockIdx.x * (SEQ / 2);
    uint32_t* pl = g_pl + (size_t)blockIdx.x * (SEQ / 2);
    __shared__ float red[8];
    const int tid = threadIdx.x, wid = tid >> 5, lane = tid & 31;

    float4 v0 = *(const float4*)(p + tid * 4);
    float4 v1 = *(const float4*)(p + 1024 + tid * 4);

    float m = fmaxf(fmaxf(fmaxf(v0.x, v0.y), fmaxf(v0.z, v0.w)),
                    fmaxf(fmaxf(v1.x, v1.y), fmaxf(v1.z, v1.w)));
#pragma unroll
    for (int o = 16; o; o >>= 1) m = fmaxf(m, __shfl_xor_sync(0xffffffffu, m, o));
    if (!lane) red[wid] = m;
    __syncthreads();
    if (tid < 32) {
        float x = (lane < 8) ? red[lane] : -1e30f;
#pragma unroll
        for (int o = 4; o; o >>= 1) x = fmaxf(x, __shfl_xor_sync(0xffffffffu, x, o));
        if (!lane) red[0] = x;
    }
    __syncthreads();
    float M = red[0];
    __syncthreads();

    v0.x = __expf(v0.x - M); v0.y = __expf(v0.y - M);
    v0.z = __expf(v0.z - M); v0.w = __expf(v0.w - M);
    v1.x = __expf(v1.x - M); v1.y = __expf(v1.y - M);
    v1.z = __expf(v1.z - M); v1.w = __expf(v1.w - M);

    float su = (v0.x + v0.y) + (v0.z + v0.w) + (v1.x + v1.y) + (v1.z + v1.w);
#pragma unroll
    for (int o = 16; o; o >>= 1) su += __shfl_xor_sync(0xffffffffu, su, o);
    if (!lane) red[wid] = su;
    __syncthreads();
    if (tid < 32) {
        float x = (lane < 8) ? red[lane] : 0.0f;
#pragma unroll
        for (int o = 4; o; o >>= 1) x += __shfl_xor_sync(0xffffffffu, x, o);
        if (!lane) red[0] = x;
    }
    __syncthreads();
    float inv = 1.0f / red[0];

    v0.x *= inv; v0.y *= inv; v0.z *= inv; v0.w *= inv;
    v1.x *= inv; v1.y *= inv; v1.z *= inv; v1.w *= inv;

    uint2 h, l;
    cvt2(v0.x, v0.y, h.x, l.x);
    cvt2(v0.z, v0.w, h.y, l.y);
    *(uint2*)(ph + tid * 2) = h;
    *(uint2*)(pl + tid * 2) = l;
    cvt2(v1.x, v1.y, h.x, l.x);
    cvt2(v1.z, v1.w, h.y, l.y);
    *(uint2*)(ph + 512 + tid * 2) = h;
    *(uint2*)(pl + 512 + tid * 2) = l;
}

// ================= GEMM2: out = P @ enc (3-term split-bf16, TransB) =================
#define G2_PATW (128 * RS)
#define G2_EATW (64 * RS)
#define G2_STGW (2 * G2_PATW + 2 * G2_EATW)
#define G2_SMEM (2 * G2_STGW * 4)   // 110,592 B

__global__ void __launch_bounds__(256)
gemm2_kernel(float* __restrict__ out) {
    extern __shared__ uint32_t sm[];
    const uint32_t sb = smem_u32(sm);
    const int tid = threadIdx.x, lane = tid & 31, wid = tid >> 5;
    const int l16 = lane & 15, lhi = lane >> 4;
    const int g = lane >> 2, t = lane & 3;
    const int wm = wid >> 1, wd = wid & 1;
    const int d0 = blockIdx.x * 64, m0 = blockIdx.y * 128, bz = blockIdx.z;

    const uint32_t* Ph = g_ph + ((size_t)bz * SEQ + m0) * 1024;
    const uint32_t* Pl = g_pl + ((size_t)bz * SEQ + m0) * 1024;
    const uint32_t* Eh = g_eh + (size_t)bz * SEQ * 256 + d0 / 2;
    const uint32_t* El = g_el + (size_t)bz * SEQ * 256 + d0 / 2;
    float* Ob = out + ((size_t)bz * SEQ + m0) * DIM + d0;

    float4 acc[2][4];
#pragma unroll
    for (int a = 0; a < 2; a++)
#pragma unroll
        for (int b = 0; b < 4; b++) acc[a][b] = make_float4(0.f, 0.f, 0.f, 0.f);

    // prologue: chunk 0 -> stage 0
#pragma unroll
    for (int i = 0; i < 4; i++) {      // P: 128 rows x 8 uint4
        int idx = tid + i * 256;
        int r = idx >> 3, u = idx & 7;
        uint32_t w = r * RS + u * 4;
        size_t ga = (size_t)r * 1024 + u * 4;
        *(uint4*)(sm + w)           = *(const uint4*)(Ph + ga);
        *(uint4*)(sm + G2_PATW + w) = *(const uint4*)(Pl + ga);
    }
#pragma unroll
    for (int i = 0; i < 2; i++) {      // E: 64 k-rows x 8 uint4
        int idx = tid + i * 256;
        int r = idx >> 3, u = idx & 7;
        uint32_t w = r * RS + u * 4;
        size_t ga = (size_t)r * 256 + u * 4;
        *(uint4*)(sm + 2 * G2_PATW + w)           = *(const uint4*)(Eh + ga);
        *(uint4*)(sm + 2 * G2_PATW + G2_EATW + w) = *(const uint4*)(El + ga);
    }
    __syncthreads();

    for (int c = 0; c < 32; c++) {
        const int s = c & 1;
        uint4 vp[4], vq[4], ve[2], vf[2];
        if (c < 31) {
            int co = (c + 1) * 32;
#pragma unroll
            for (int i = 0; i < 4; i++) {
                int idx = tid + i * 256;
                int r = idx >> 3, u = idx & 7;
                size_t ga = (size_t)r * 1024 + co + u * 4;
                vp[i] = *(const uint4*)(Ph + ga);
                vq[i] = *(const uint4*)(Pl + ga);
            }
#pragma unroll
            for (int i = 0; i < 2; i++) {
                int idx = tid + i * 256;
                int r = idx >> 3, u = idx & 7;
                size_t ga = (size_t)((c + 1) * 64 + r) * 256 + u * 4;
                ve[i] = *(const uint4*)(Eh + ga);
                vf[i] = *(const uint4*)(El + ga);
            }
        }
        // ---- mma over stage s (verbatim v12) ----
        {
            const uint32_t base = sb + (uint32_t)s * (G2_STGW * 4);
            const uint32_t aP  = base + (uint32_t)(wm * 32 + l16) * 144 + lhi * 16;
            const uint32_t aPl = aP + G2_PATW * 4;
            const uint32_t aE  = base + 2u * G2_PATW * 4 + (uint32_t)l16 * 144 + wd * 64 + lhi * 16;
            const uint32_t aEl = aE + G2_EATW * 4;
#pragma unroll
            for (int st = 0; st < 4; st++) {
                uint32_t ph[2][4], pl2[2][4];
#pragma unroll
                for (int mt = 0; mt < 2; mt++) {
                    ldsm4(ph[mt][0], ph[mt][1], ph[mt][2], ph[mt][3], aP + mt * 2304 + st * 32);
                    ldsm4(pl2[mt][0], pl2[mt][1], pl2[mt][2], pl2[mt][3], aPl + mt * 2304 + st * 32);
                }
                uint32_t eh[8], el[8];
                ldsm4t(eh[0], eh[1], eh[2], eh[3], aE + st * 2304);
                ldsm4t(eh[4], eh[5], eh[6], eh[7], aE + st * 2304 + 32);
                ldsm4t(el[0], el[1], el[2], el[3], aEl + st * 2304);
                ldsm4t(el[4], el[5], el[6], el[7], aEl + st * 2304 + 32);
#pragma unroll
                for (int mt = 0; mt < 2; mt++)
#pragma unroll
                    for (int np = 0; np < 4; np++) {
                        mma16(acc[mt][np], ph[mt][0], ph[mt][1], ph[mt][2], ph[mt][3],
                              el[np * 2], el[np * 2 + 1]);
                        mma16(acc[mt][np], pl2[mt][0], pl2[mt][1], pl2[mt][2], pl2[mt][3],
                              eh[np * 2], eh[np * 2 + 1]);
                        mma16(acc[mt][np], ph[mt][0], ph[mt][1], ph[mt][2], ph[mt][3],
                              eh[np * 2], eh[np * 2 + 1]);
                    }
            }
        }
        // ---- STS next chunk ----
        if (c < 31) {
            uint32_t* stg = sm + (uint32_t)(s ^ 1) * G2_STGW;
#pragma unroll
            for (int i = 0; i < 4; i++) {
                int idx = tid + i * 256;
                int r = idx >> 3, u = idx & 7;
                uint32_t w = r * RS + u * 4;
                *(uint4*)(stg + w)           = vp[i];
                *(uint4*)(stg + G2_PATW + w) = vq[i];
            }
#pragma unroll
            for (int i = 0; i < 2; i++) {
                int idx = tid + i * 256;
                int r = idx >> 3, u = idx & 7;
                uint32_t w = r * RS + u * 4;
                *(uint4*)(stg + 2 * G2_PATW + w)           = ve[i];
                *(uint4*)(stg + 2 * G2_PATW + G2_EATW + w) = vf[i];
            }
        }
        __syncthreads();
    }

#pragma unroll
    for (int mt = 0; mt < 2; mt++) {
        int r = wm * 32 + mt * 16 + g;
#pragma unroll
        for (int np = 0; np < 4; np++) {
            int cc = wd * 32 + np * 8 + (t << 1);
            *(float2*)(Ob + (size_t)r * DIM + cc)       = make_float2(acc[mt][np].x, acc[mt][np].y);
            *(float2*)(Ob + (size_t)(r + 8) * DIM + cc) = make_float2(acc[mt][np].z, acc[mt][np].w);
        }
    }
}

// ================= launch =================
extern "C" void kernel_launch(void* const* d_in, const int* in_sizes, int n_in,
                              void* d_out, int out_size) {
    const float* enc = (const float*)d_in[0];   // enc_outputs [8,2048,512]
    const float* dec = (const float*)d_in[1];   // dec_outputs [8,2048,512]
    float* out = (float*)d_out;                 // [8,2048,512]

    float* S = nullptr;
    cudaGetSymbolAddress((void**)&S, g_S);

    cudaFuncSetAttribute(gemm1_kernel, cudaFuncAttributeMaxDynamicSharedMemorySize, G1_SMEM);
    cudaFuncSetAttribute(gemm2_kernel, cudaFuncAttributeMaxDynamicSharedMemorySize, G2_SMEM);

    split_kernel<<<dim3(4096, 2), 256>>>(enc, dec);
    gemm1_kernel<<<dim3(16, 16, NB), 256, G1_SMEM>>>(S);
    softmax_kernel<<<NB * SEQ, 256>>>();
    gemm2_kernel<<<dim3(8, 16, NB), 256, G2_SMEM>>>(out);
}

// round 14
// speedup vs baseline: 1.4517x; 1.0418x over previous
#include <cuda_runtime.h>
#include <cuda_bf16.h>
#include <cstdint>

#define SEQ 2048
#define DIM 512
#define NB  8

// device scratch: S fp32 + pair-packed split-bf16 operands
__device__ float    g_S [(size_t)NB * SEQ * SEQ];
__device__ uint32_t g_eh[(size_t)NB * SEQ * (DIM / 2)];
__device__ uint32_t g_el[(size_t)NB * SEQ * (DIM / 2)];
__device__ uint32_t g_dh[(size_t)NB * SEQ * (DIM / 2)];
__device__ uint32_t g_dl[(size_t)NB * SEQ * (DIM / 2)];
__device__ uint32_t g_ph[(size_t)NB * SEQ * (SEQ / 2)];
__device__ uint32_t g_pl[(size_t)NB * SEQ * (SEQ / 2)];

// ---------------- helpers ----------------
__device__ __forceinline__ uint32_t smem_u32(const void* p) {
    uint32_t a;
    asm("{ .reg .u64 t; cvta.to.shared.u64 t, %1; cvt.u32.u64 %0, t; }" : "=r"(a) : "l"(p));
    return a;
}

__device__ __forceinline__ void cvt2(float x, float y, uint32_t& hip, uint32_t& lop) {
    __nv_bfloat16 bx = __float2bfloat16_rn(x);
    __nv_bfloat16 by = __float2bfloat16_rn(y);
    float rx = x - __bfloat162float(bx);
    float ry = y - __bfloat162float(by);
    __nv_bfloat162 h; h.x = bx; h.y = by;
    __nv_bfloat162 l; l.x = __float2bfloat16_rn(rx); l.y = __float2bfloat16_rn(ry);
    hip = *reinterpret_cast<uint32_t*>(&h);
    lop = *reinterpret_cast<uint32_t*>(&l);
}

__device__ __forceinline__ void mma16(float4& d,
                                      uint32_t a0, uint32_t a1, uint32_t a2, uint32_t a3,
                                      uint32_t b0, uint32_t b1) {
    asm volatile(
        "mma.sync.aligned.m16n8k16.row.col.f32.bf16.bf16.f32 "
        "{%0,%1,%2,%3},{%4,%5,%6,%7},{%8,%9},{%0,%1,%2,%3};"
        : "+f"(d.x), "+f"(d.y), "+f"(d.z), "+f"(d.w)
        : "r"(a0), "r"(a1), "r"(a2), "r"(a3), "r"(b0), "r"(b1));
}

__device__ __forceinline__ void ldsm4(uint32_t& r0, uint32_t& r1, uint32_t& r2, uint32_t& r3,
                                      uint32_t a) {
    asm volatile("ldmatrix.sync.aligned.m8n8.x4.shared.b16 {%0,%1,%2,%3}, [%4];"
                 : "=r"(r0), "=r"(r1), "=r"(r2), "=r"(r3) : "r"(a));
}
__device__ __forceinline__ void ldsm4t(uint32_t& r0, uint32_t& r1, uint32_t& r2, uint32_t& r3,
                                       uint32_t a) {
    asm volatile("ldmatrix.sync.aligned.m8n8.x4.trans.shared.b16 {%0,%1,%2,%3}, [%4];"
                 : "=r"(r0), "=r"(r1), "=r"(r2), "=r"(r3) : "r"(a));
}

__device__ __forceinline__ void cpa16(uint32_t saddr, const void* g) {
    asm volatile("cp.async.cg.shared.global [%0], [%1], 16;" :: "r"(saddr), "l"(g));
}
__device__ __forceinline__ void cpa_commit() {
    asm volatile("cp.async.commit_group;" ::: "memory");
}
__device__ __forceinline__ void cpa_wait0() {
    asm volatile("cp.async.wait_group 0;" ::: "memory");
}

#define RS  36   // words per 32-pair row (144 B)
#define RS2 68   // words per 64-pair row (272 B)

// ================= split kernel =================
__global__ void __launch_bounds__(256)
split_kernel(const float* __restrict__ enc, const float* __restrict__ dec) {
    const size_t t = (size_t)blockIdx.x * 256 + threadIdx.x;
    const float* src = blockIdx.y ? dec : enc;
    uint32_t* dh = blockIdx.y ? g_dh : g_eh;
    uint32_t* dl = blockIdx.y ? g_dl : g_el;
    float4 v0 = *(const float4*)(src + t * 8);
    float4 v1 = *(const float4*)(src + t * 8 + 4);
    uint4 h, l;
    cvt2(v0.x, v0.y, h.x, l.x);
    cvt2(v0.z, v0.w, h.y, l.y);
    cvt2(v1.x, v1.y, h.z, l.z);
    cvt2(v1.z, v1.w, h.w, l.w);
    *(uint4*)(dh + t * 4) = h;
    *(uint4*)(dl + t * 4) = l;
}

// ================= GEMM1: S = dec @ enc^T, CTA 256x128, cp.async staging =================
#define G1_AW   (256 * RS)                 // 9216 words per A matrix
#define G1_BW   (128 * RS)                 // 4608 words per B matrix
#define G1_STGW (2 * G1_AW + 2 * G1_BW)    // 27648 words
#define G1_SMEM (2 * G1_STGW * 4)          // 221,184 B

__global__ void __launch_bounds__(256)
gemm1_kernel(float* __restrict__ S) {
    extern __shared__ uint32_t sm[];
    const uint32_t sb = smem_u32(sm);
    const int tid = threadIdx.x, lane = tid & 31, wid = tid >> 5;
    const int l16 = lane & 15, lhi = lane >> 4, l8 = lane & 7, mi = lane >> 3;
    const int g = lane >> 2, t = lane & 3;
    const int wm = wid >> 1, wn = wid & 1;          // warp tile 64m x 64n
    const int n0 = blockIdx.x * 128, m0 = blockIdx.y * 256, bz = blockIdx.z;

    const uint32_t* Ah = g_dh + ((size_t)bz * SEQ + m0) * 256;
    const uint32_t* Al = g_dl + ((size_t)bz * SEQ + m0) * 256;
    const uint32_t* Bh = g_eh + ((size_t)bz * SEQ + n0) * 256;
    const uint32_t* Bl = g_el + ((size_t)bz * SEQ + n0) * 256;
    float* Cb = S + (size_t)bz * SEQ * SEQ + (size_t)m0 * SEQ + n0;

    float4 acc[4][8];
#pragma unroll
    for (int a = 0; a < 4; a++)
#pragma unroll
        for (int b = 0; b < 8; b++) acc[a][b] = make_float4(0.f, 0.f, 0.f, 0.f);

    // cp.async loader: chunk c (32 pairs) -> stage at byte base stg
    auto load1 = [&](int c, uint32_t stg) {
        const int co = c * 32;
#pragma unroll
        for (int i = 0; i < 8; i++) {                 // A: 256 rows x 8 uint4
            int idx = tid + i * 256;
            int r = idx >> 3, u = idx & 7;
            uint32_t sa = stg + (uint32_t)(r * RS + u * 4) * 4;
            cpa16(sa, Ah + (size_t)r * 256 + co + u * 4);
            cpa16(sa + G1_AW * 4, Al + (size_t)r * 256 + co + u * 4);
        }
#pragma unroll
        for (int i = 0; i < 4; i++) {                 // B: 128 rows x 8 uint4
            int idx = tid + i * 256;
            int r = idx >> 3, u = idx & 7;
            uint32_t sa = stg + (uint32_t)(2 * G1_AW + r * RS + u * 4) * 4;
            cpa16(sa, Bh + (size_t)r * 256 + co + u * 4);
            cpa16(sa + G1_BW * 4, Bl + (size_t)r * 256 + co + u * 4);
        }
        cpa_commit();
    };

    load1(0, sb);
    cpa_wait0();
    __syncthreads();

    for (int c = 0; c < 8; c++) {
        const int s = c & 1;
        if (c < 7) load1(c + 1, sb + (uint32_t)(s ^ 1) * (G1_STGW * 4));

        const uint32_t base = sb + (uint32_t)s * (G1_STGW * 4);
        const uint32_t aA  = base + (uint32_t)(wm * 64 + l16) * 144 + lhi * 16;
        const uint32_t aAl = aA + G1_AW * 4;
        const uint32_t aB  = base + 2u * G1_AW * 4 +
                             (uint32_t)(wn * 64 + (mi >> 1) * 8 + l8) * 144 + (mi & 1) * 16;
        const uint32_t aBl = aB + G1_BW * 4;
#pragma unroll
        for (int st = 0; st < 4; st++) {
            uint32_t ah[4][4], al[4][4];
#pragma unroll
            for (int mt = 0; mt < 4; mt++) {
                ldsm4(ah[mt][0], ah[mt][1], ah[mt][2], ah[mt][3], aA + mt * 2304 + st * 32);
                ldsm4(al[mt][0], al[mt][1], al[mt][2], al[mt][3], aAl + mt * 2304 + st * 32);
            }
            uint32_t bh[16], bl[16];
#pragma unroll
            for (int q = 0; q < 4; q++) {
                ldsm4(bh[q * 4], bh[q * 4 + 1], bh[q * 4 + 2], bh[q * 4 + 3],
                      aB + q * 16 * 144 + st * 32);
                ldsm4(bl[q * 4], bl[q * 4 + 1], bl[q * 4 + 2], bl[q * 4 + 3],
                      aBl + q * 16 * 144 + st * 32);
            }
#pragma unroll
            for (int mt = 0; mt < 4; mt++)
#pragma unroll
                for (int np = 0; np < 8; np++) {
                    mma16(acc[mt][np], ah[mt][0], ah[mt][1], ah[mt][2], ah[mt][3],
                          bl[np * 2], bl[np * 2 + 1]);
                    mma16(acc[mt][np], al[mt][0], al[mt][1], al[mt][2], al[mt][3],
                          bh[np * 2], bh[np * 2 + 1]);
                    mma16(acc[mt][np], ah[mt][0], ah[mt][1], ah[mt][2], ah[mt][3],
                          bh[np * 2], bh[np * 2 + 1]);
                }
        }
        cpa_wait0();
        __syncthreads();
    }

#pragma unroll
    for (int mt = 0; mt < 4; mt++) {
        int r = wm * 64 + mt * 16 + g;
#pragma unroll
        for (int np = 0; np < 8; np++) {
            int cc = wn * 64 + np * 8 + (t << 1);
            *(float2*)(Cb + (size_t)r * SEQ + cc)       = make_float2(acc[mt][np].x, acc[mt][np].y);
            *(float2*)(Cb + (size_t)(r + 8) * SEQ + cc) = make_float2(acc[mt][np].z, acc[mt][np].w);
        }
    }
}

// ================= softmax: S row -> pair-packed split-bf16 P =================
__global__ void __launch_bounds__(256)
softmax_kernel() {
    const float* p = g_S + (size_t)blockIdx.x * SEQ;
    uint32_t* ph = g_ph + (size_t)blockIdx.x * (SEQ / 2);
    uint32_t* pl = g_pl + (size_t)blockIdx.x * (SEQ / 2);
    __shared__ float red[8];
    const int tid = threadIdx.x, wid = tid >> 5, lane = tid & 31;

    float4 v0 = *(const float4*)(p + tid * 4);
    float4 v1 = *(const float4*)(p + 1024 + tid * 4);

    float m = fmaxf(fmaxf(fmaxf(v0.x, v0.y), fmaxf(v0.z, v0.w)),
                    fmaxf(fmaxf(v1.x, v1.y), fmaxf(v1.z, v1.w)));
#pragma unroll
    for (int o = 16; o; o >>= 1) m = fmaxf(m, __shfl_xor_sync(0xffffffffu, m, o));
    if (!lane) red[wid] = m;
    __syncthreads();
    if (tid < 32) {
        float x = (lane < 8) ? red[lane] : -1e30f;
#pragma unroll
        for (int o = 4; o; o >>= 1) x = fmaxf(x, __shfl_xor_sync(0xffffffffu, x, o));
        if (!lane) red[0] = x;
    }
    __syncthreads();
    float M = red[0];
    __syncthreads();

    v0.x = __expf(v0.x - M); v0.y = __expf(v0.y - M);
    v0.z = __expf(v0.z - M); v0.w = __expf(v0.w - M);
    v1.x = __expf(v1.x - M); v1.y = __expf(v1.y - M);
    v1.z = __expf(v1.z - M); v1.w = __expf(v1.w - M);

    float su = (v0.x + v0.y) + (v0.z + v0.w) + (v1.x + v1.y) + (v1.z + v1.w);
#pragma unroll
    for (int o = 16; o; o >>= 1) su += __shfl_xor_sync(0xffffffffu, su, o);
    if (!lane) red[wid] = su;
    __syncthreads();
    if (tid < 32) {
        float x = (lane < 8) ? red[lane] : 0.0f;
#pragma unroll
        for (int o = 4; o; o >>= 1) x += __shfl_xor_sync(0xffffffffu, x, o);
        if (!lane) red[0] = x;
    }
    __syncthreads();
    float inv = 1.0f / red[0];

    v0.x *= inv; v0.y *= inv; v0.z *= inv; v0.w *= inv;
    v1.x *= inv; v1.y *= inv; v1.z *= inv; v1.w *= inv;

    uint2 h, l;
    cvt2(v0.x, v0.y, h.x, l.x);
    cvt2(v0.z, v0.w, h.y, l.y);
    *(uint2*)(ph + tid * 2) = h;
    *(uint2*)(pl + tid * 2) = l;
    cvt2(v1.x, v1.y, h.x, l.x);
    cvt2(v1.z, v1.w, h.y, l.y);
    *(uint2*)(ph + 512 + tid * 2) = h;
    *(uint2*)(pl + 512 + tid * 2) = l;
}

// ================= GEMM2: out = P @ enc, CTA 128x128, cp.async staging =================
#define G2_PW   (128 * RS)                 // 4608 words per P matrix
#define G2_EW   (64 * RS2)                 // 4352 words per E matrix
#define G2_STGW (2 * G2_PW + 2 * G2_EW)    // 17920 words
#define G2_SMEM (2 * G2_STGW * 4)          // 143,360 B

__global__ void __launch_bounds__(256)
gemm2_kernel(float* __restrict__ out) {
    extern __shared__ uint32_t sm[];
    const uint32_t sb = smem_u32(sm);
    const int tid = threadIdx.x, lane = tid & 31, wid = tid >> 5;
    const int l16 = lane & 15, lhi = lane >> 4;
    const int g = lane >> 2, t = lane & 3;
    const int wm = wid >> 1, wd = wid & 1;          // warp tile 32m x 64d
    const int d0 = blockIdx.x * 128, m0 = blockIdx.y * 128, bz = blockIdx.z;

    const uint32_t* Ph = g_ph + ((size_t)bz * SEQ + m0) * 1024;
    const uint32_t* Pl = g_pl + ((size_t)bz * SEQ + m0) * 1024;
    const uint32_t* Eh = g_eh + (size_t)bz * SEQ * 256 + d0 / 2;
    const uint32_t* El = g_el + (size_t)bz * SEQ * 256 + d0 / 2;
    float* Ob = out + ((size_t)bz * SEQ + m0) * DIM + d0;

    float4 acc[2][8];
#pragma unroll
    for (int a = 0; a < 2; a++)
#pragma unroll
        for (int b = 0; b < 8; b++) acc[a][b] = make_float4(0.f, 0.f, 0.f, 0.f);

    auto load2 = [&](int c, uint32_t stg) {
#pragma unroll
        for (int i = 0; i < 4; i++) {                 // P: 128 rows x 8 uint4
            int idx = tid + i * 256;
            int r = idx >> 3, u = idx & 7;
            uint32_t sa = stg + (uint32_t)(r * RS + u * 4) * 4;
            cpa16(sa, Ph + (size_t)r * 1024 + c * 32 + u * 4);
            cpa16(sa + G2_PW * 4, Pl + (size_t)r * 1024 + c * 32 + u * 4);
        }
#pragma unroll
        for (int i = 0; i < 4; i++) {                 // E: 64 rows x 16 uint4
            int idx = tid + i * 256;
            int r = idx >> 4, u = idx & 15;
            uint32_t sa = stg + (uint32_t)(2 * G2_PW + r * RS2 + u * 4) * 4;
            cpa16(sa, Eh + (size_t)(c * 64 + r) * 256 + u * 4);
            cpa16(sa + G2_EW * 4, El + (size_t)(c * 64 + r) * 256 + u * 4);
        }
        cpa_commit();
    };

    load2(0, sb);
    cpa_wait0();
    __syncthreads();

    for (int c = 0; c < 32; c++) {
        const int s = c & 1;
        if (c < 31) load2(c + 1, sb + (uint32_t)(s ^ 1) * (G2_STGW * 4));

        const uint32_t base = sb + (uint32_t)s * (G2_STGW * 4);
        const uint32_t aP  = base + (uint32_t)(wm * 32 + l16) * 144 + lhi * 16;
        const uint32_t aPl = aP + G2_PW * 4;
        const uint32_t aE  = base + 2u * G2_PW * 4 + (uint32_t)l16 * 272 + wd * 128 + lhi * 16;
        const uint32_t aEl = aE + G2_EW * 4;
#pragma unroll
        for (int st = 0; st < 4; st++) {
            uint32_t ph[2][4], pl2[2][4];
#pragma unroll
            for (int mt = 0; mt < 2; mt++) {
                ldsm4(ph[mt][0], ph[mt][1], ph[mt][2], ph[mt][3], aP + mt * 2304 + st * 32);
                ldsm4(pl2[mt][0], pl2[mt][1], pl2[mt][2], pl2[mt][3], aPl + mt * 2304 + st * 32);
            }
            uint32_t eh[16], el[16];
#pragma unroll
            for (int q = 0; q < 4; q++) {
                ldsm4t(eh[q * 4], eh[q * 4 + 1], eh[q * 4 + 2], eh[q * 4 + 3],
                       aE + st * (16 * 272) + q * 32);
                ldsm4t(el[q * 4], el[q * 4 + 1], el[q * 4 + 2], el[q * 4 + 3],
                       aEl + st * (16 * 272) + q * 32);
            }
#pragma unroll
            for (int mt = 0; mt < 2; mt++)
#pragma unroll
                for (int np = 0; np < 8; np++) {
                    mma16(acc[mt][np], ph[mt][0], ph[mt][1], ph[mt][2], ph[mt][3],
                          el[np * 2], el[np * 2 + 1]);
                    mma16(acc[mt][np], pl2[mt][0], pl2[mt][1], pl2[mt][2], pl2[mt][3],
                          eh[np * 2], eh[np * 2 + 1]);
                    mma16(acc[mt][np], ph[mt][0], ph[mt][1], ph[mt][2], ph[mt][3],
                          eh[np * 2], eh[np * 2 + 1]);
                }
        }
        cpa_wait0();
        __syncthreads();
    }

#pragma unroll
    for (int mt = 0; mt < 2; mt++) {
        int r = wm * 32 + mt * 16 + g;
#pragma unroll
        for (int np = 0; np < 8; np++) {
            int cc = wd * 64 + np * 8 + (t << 1);
            *(float2*)(Ob + (size_t)r * DIM + cc)       = make_float2(acc[mt][np].x, acc[mt][np].y);
            *(float2*)(Ob + (size_t)(r + 8) * DIM + cc) = make_float2(acc[mt][np].z, acc[mt][np].w);
        }
    }
}

// ================= launch =================
extern "C" void kernel_launch(void* const* d_in, const int* in_sizes, int n_in,
                              void* d_out, int out_size) {
    const float* enc = (const float*)d_in[0];   // enc_outputs [8,2048,512]
    const float* dec = (const float*)d_in[1];   // dec_outputs [8,2048,512]
    float* out = (float*)d_out;                 // [8,2048,512]

    float* S = nullptr;
    cudaGetSymbolAddress((void**)&S, g_S);

    cudaFuncSetAttribute(gemm1_kernel, cudaFuncAttributeMaxDynamicSharedMemorySize, G1_SMEM);
    cudaFuncSetAttribute(gemm2_kernel, cudaFuncAttributeMaxDynamicSharedMemorySize, G2_SMEM);

    split_kernel<<<dim3(4096, 2), 256>>>(enc, dec);
    gemm1_kernel<<<dim3(16, 8, NB), 256, G1_SMEM>>>(S);
    softmax_kernel<<<NB * SEQ, 256>>>();
    gemm2_kernel<<<dim3(4, 16, NB), 256, G2_SMEM>>>(out);
}

// round 15
// speedup vs baseline: 1.4572x; 1.0038x over previous
#include <cuda_runtime.h>
#include <cuda_bf16.h>
#include <cstdint>

#define SEQ 2048
#define DIM 512
#define NB  8

// device scratch: S fp32 + pair-packed split-bf16 operands
__device__ float    g_S [(size_t)NB * SEQ * SEQ];
__device__ uint32_t g_eh[(size_t)NB * SEQ * (DIM / 2)];
__device__ uint32_t g_el[(size_t)NB * SEQ * (DIM / 2)];
__device__ uint32_t g_dh[(size_t)NB * SEQ * (DIM / 2)];
__device__ uint32_t g_dl[(size_t)NB * SEQ * (DIM / 2)];
__device__ uint32_t g_ph[(size_t)NB * SEQ * (SEQ / 2)];
__device__ uint32_t g_pl[(size_t)NB * SEQ * (SEQ / 2)];

// ---------------- helpers ----------------
__device__ __forceinline__ uint32_t smem_u32(const void* p) {
    uint32_t a;
    asm("{ .reg .u64 t; cvta.to.shared.u64 t, %1; cvt.u32.u64 %0, t; }" : "=r"(a) : "l"(p));
    return a;
}

__device__ __forceinline__ void cvt2(float x, float y, uint32_t& hip, uint32_t& lop) {
    __nv_bfloat16 bx = __float2bfloat16_rn(x);
    __nv_bfloat16 by = __float2bfloat16_rn(y);
    float rx = x - __bfloat162float(bx);
    float ry = y - __bfloat162float(by);
    __nv_bfloat162 h; h.x = bx; h.y = by;
    __nv_bfloat162 l; l.x = __float2bfloat16_rn(rx); l.y = __float2bfloat16_rn(ry);
    hip = *reinterpret_cast<uint32_t*>(&h);
    lop = *reinterpret_cast<uint32_t*>(&l);
}

__device__ __forceinline__ void mma16(float4& d,
                                      uint32_t a0, uint32_t a1, uint32_t a2, uint32_t a3,
                                      uint32_t b0, uint32_t b1) {
    asm volatile(
        "mma.sync.aligned.m16n8k16.row.col.f32.bf16.bf16.f32 "
        "{%0,%1,%2,%3},{%4,%5,%6,%7},{%8,%9},{%0,%1,%2,%3};"
        : "+f"(d.x), "+f"(d.y), "+f"(d.z), "+f"(d.w)
        : "r"(a0), "r"(a1), "r"(a2), "r"(a3), "r"(b0), "r"(b1));
}

__device__ __forceinline__ void ldsm4(uint32_t& r0, uint32_t& r1, uint32_t& r2, uint32_t& r3,
                                      uint32_t a) {
    asm volatile("ldmatrix.sync.aligned.m8n8.x4.shared.b16 {%0,%1,%2,%3}, [%4];"
                 : "=r"(r0), "=r"(r1), "=r"(r2), "=r"(r3) : "r"(a));
}
__device__ __forceinline__ void ldsm4t(uint32_t& r0, uint32_t& r1, uint32_t& r2, uint32_t& r3,
                                       uint32_t a) {
    asm volatile("ldmatrix.sync.aligned.m8n8.x4.trans.shared.b16 {%0,%1,%2,%3}, [%4];"
                 : "=r"(r0), "=r"(r1), "=r"(r2), "=r"(r3) : "r"(a));
}

__device__ __forceinline__ void cpa16(uint32_t saddr, const void* g) {
    asm volatile("cp.async.cg.shared.global [%0], [%1], 16;" :: "r"(saddr), "l"(g));
}
__device__ __forceinline__ void cpa_commit() {
    asm volatile("cp.async.commit_group;" ::: "memory");
}
__device__ __forceinline__ void cpa_wait0() {
    asm volatile("cp.async.wait_group 0;" ::: "memory");
}

#define RS  36   // words per 32-pair row (144 B)
#define RS2 68   // words per 64-pair row (272 B)
#define RS3 20   // words per 16-pair row (80 B)

// ================= split kernel =================
__global__ void __launch_bounds__(256)
split_kernel(const float* __restrict__ enc, const float* __restrict__ dec) {
    const size_t t = (size_t)blockIdx.x * 256 + threadIdx.x;
    const float* src = blockIdx.y ? dec : enc;
    uint32_t* dh = blockIdx.y ? g_dh : g_eh;
    uint32_t* dl = blockIdx.y ? g_dl : g_el;
    float4 v0 = *(const float4*)(src + t * 8);
    float4 v1 = *(const float4*)(src + t * 8 + 4);
    uint4 h, l;
    cvt2(v0.x, v0.y, h.x, l.x);
    cvt2(v0.z, v0.w, h.y, l.y);
    cvt2(v1.x, v1.y, h.z, l.z);
    cvt2(v1.z, v1.w, h.w, l.w);
    *(uint4*)(dh + t * 4) = h;
    *(uint4*)(dl + t * 4) = l;
}

// ================= GEMM1: S = dec @ enc^T, CTA 256x128, cp.async staging =================
#define G1_AW   (256 * RS)
#define G1_BW   (128 * RS)
#define G1_STGW (2 * G1_AW + 2 * G1_BW)
#define G1_SMEM (2 * G1_STGW * 4)   // 221,184 B

__global__ void __launch_bounds__(256)
gemm1_kernel(float* __restrict__ S) {
    extern __shared__ uint32_t sm[];
    const uint32_t sb = smem_u32(sm);
    const int tid = threadIdx.x, lane = tid & 31, wid = tid >> 5;
    const int l16 = lane & 15, lhi = lane >> 4, l8 = lane & 7, mi = lane >> 3;
    const int g = lane >> 2, t = lane & 3;
    const int wm = wid >> 1, wn = wid & 1;
    const int n0 = blockIdx.x * 128, m0 = blockIdx.y * 256, bz = blockIdx.z;

    const uint32_t* Ah = g_dh + ((size_t)bz * SEQ + m0) * 256;
    const uint32_t* Al = g_dl + ((size_t)bz * SEQ + m0) * 256;
    const uint32_t* Bh = g_eh + ((size_t)bz * SEQ + n0) * 256;
    const uint32_t* Bl = g_el + ((size_t)bz * SEQ + n0) * 256;
    float* Cb = S + (size_t)bz * SEQ * SEQ + (size_t)m0 * SEQ + n0;

    float4 acc[4][8];
#pragma unroll
    for (int a = 0; a < 4; a++)
#pragma unroll
        for (int b = 0; b < 8; b++) acc[a][b] = make_float4(0.f, 0.f, 0.f, 0.f);

    auto load1 = [&](int c, uint32_t stg) {
        const int co = c * 32;
#pragma unroll
        for (int i = 0; i < 8; i++) {
            int idx = tid + i * 256;
            int r = idx >> 3, u = idx & 7;
            uint32_t sa = stg + (uint32_t)(r * RS + u * 4) * 4;
            cpa16(sa, Ah + (size_t)r * 256 + co + u * 4);
            cpa16(sa + G1_AW * 4, Al + (size_t)r * 256 + co + u * 4);
        }
#pragma unroll
        for (int i = 0; i < 4; i++) {
            int idx = tid + i * 256;
            int r = idx >> 3, u = idx & 7;
            uint32_t sa = stg + (uint32_t)(2 * G1_AW + r * RS + u * 4) * 4;
            cpa16(sa, Bh + (size_t)r * 256 + co + u * 4);
            cpa16(sa + G1_BW * 4, Bl + (size_t)r * 256 + co + u * 4);
        }
        cpa_commit();
    };

    load1(0, sb);
    cpa_wait0();
    __syncthreads();

    for (int c = 0; c < 8; c++) {
        const int s = c & 1;
        if (c < 7) load1(c + 1, sb + (uint32_t)(s ^ 1) * (G1_STGW * 4));

        const uint32_t base = sb + (uint32_t)s * (G1_STGW * 4);
        const uint32_t aA  = base + (uint32_t)(wm * 64 + l16) * 144 + lhi * 16;
        const uint32_t aAl = aA + G1_AW * 4;
        const uint32_t aB  = base + 2u * G1_AW * 4 +
                             (uint32_t)(wn * 64 + (mi >> 1) * 8 + l8) * 144 + (mi & 1) * 16;
        const uint32_t aBl = aB + G1_BW * 4;
#pragma unroll
        for (int st = 0; st < 4; st++) {
            uint32_t ah[4][4], al[4][4];
#pragma unroll
            for (int mt = 0; mt < 4; mt++) {
                ldsm4(ah[mt][0], ah[mt][1], ah[mt][2], ah[mt][3], aA + mt * 2304 + st * 32);
                ldsm4(al[mt][0], al[mt][1], al[mt][2], al[mt][3], aAl + mt * 2304 + st * 32);
            }
            uint32_t bh[16], bl[16];
#pragma unroll
            for (int q = 0; q < 4; q++) {
                ldsm4(bh[q * 4], bh[q * 4 + 1], bh[q * 4 + 2], bh[q * 4 + 3],
                      aB + q * 16 * 144 + st * 32);
                ldsm4(bl[q * 4], bl[q * 4 + 1], bl[q * 4 + 2], bl[q * 4 + 3],
                      aBl + q * 16 * 144 + st * 32);
            }
#pragma unroll
            for (int mt = 0; mt < 4; mt++)
#pragma unroll
                for (int np = 0; np < 8; np++) {
                    mma16(acc[mt][np], ah[mt][0], ah[mt][1], ah[mt][2], ah[mt][3],
                          bl[np * 2], bl[np * 2 + 1]);
                    mma16(acc[mt][np], al[mt][0], al[mt][1], al[mt][2], al[mt][3],
                          bh[np * 2], bh[np * 2 + 1]);
                    mma16(acc[mt][np], ah[mt][0], ah[mt][1], ah[mt][2], ah[mt][3],
                          bh[np * 2], bh[np * 2 + 1]);
                }
        }
        cpa_wait0();
        __syncthreads();
    }

#pragma unroll
    for (int mt = 0; mt < 4; mt++) {
        int r = wm * 64 + mt * 16 + g;
#pragma unroll
        for (int np = 0; np < 8; np++) {
            int cc = wn * 64 + np * 8 + (t << 1);
            *(float2*)(Cb + (size_t)r * SEQ + cc)       = make_float2(acc[mt][np].x, acc[mt][np].y);
            *(float2*)(Cb + (size_t)(r + 8) * SEQ + cc) = make_float2(acc[mt][np].z, acc[mt][np].w);
        }
    }
}

// ================= softmax: S row -> pair-packed split-bf16 P =================
__global__ void __launch_bounds__(256)
softmax_kernel() {
    const float* p = g_S + (size_t)blockIdx.x * SEQ;
    uint32_t* ph = g_ph + (size_t)blockIdx.x * (SEQ / 2);
    uint32_t* pl = g_pl + (size_t)blockIdx.x * (SEQ / 2);
    __shared__ float red[8];
    const int tid = threadIdx.x, wid = tid >> 5, lane = tid & 31;

    float4 v0 = *(const float4*)(p + tid * 4);
    float4 v1 = *(const float4*)(p + 1024 + tid * 4);

    float m = fmaxf(fmaxf(fmaxf(v0.x, v0.y), fmaxf(v0.z, v0.w)),
                    fmaxf(fmaxf(v1.x, v1.y), fmaxf(v1.z, v1.w)));
#pragma unroll
    for (int o = 16; o; o >>= 1) m = fmaxf(m, __shfl_xor_sync(0xffffffffu, m, o));
    if (!lane) red[wid] = m;
    __syncthreads();
    if (tid < 32) {
        float x = (lane < 8) ? red[lane] : -1e30f;
#pragma unroll
        for (int o = 4; o; o >>= 1) x = fmaxf(x, __shfl_xor_sync(0xffffffffu, x, o));
        if (!lane) red[0] = x;
    }
    __syncthreads();
    float M = red[0];
    __syncthreads();

    v0.x = __expf(v0.x - M); v0.y = __expf(v0.y - M);
    v0.z = __expf(v0.z - M); v0.w = __expf(v0.w - M);
    v1.x = __expf(v1.x - M); v1.y = __expf(v1.y - M);
    v1.z = __expf(v1.z - M); v1.w = __expf(v1.w - M);

    float su = (v0.x + v0.y) + (v0.z + v0.w) + (v1.x + v1.y) + (v1.z + v1.w);
#pragma unroll
    for (int o = 16; o; o >>= 1) su += __shfl_xor_sync(0xffffffffu, su, o);
    if (!lane) red[wid] = su;
    __syncthreads();
    if (tid < 32) {
        float x = (lane < 8) ? red[lane] : 0.0f;
#pragma unroll
        for (int o = 4; o; o >>= 1) x += __shfl_xor_sync(0xffffffffu, x, o);
        if (!lane) red[0] = x;
    }
    __syncthreads();
    float inv = 1.0f / red[0];

    v0.x *= inv; v0.y *= inv; v0.z *= inv; v0.w *= inv;
    v1.x *= inv; v1.y *= inv; v1.z *= inv; v1.w *= inv;

    uint2 h, l;
    cvt2(v0.x, v0.y, h.x, l.x);
    cvt2(v0.z, v0.w, h.y, l.y);
    *(uint2*)(ph + tid * 2) = h;
    *(uint2*)(pl + tid * 2) = l;
    cvt2(v1.x, v1.y, h.x, l.x);
    cvt2(v1.z, v1.w, h.y, l.y);
    *(uint2*)(ph + 512 + tid * 2) = h;
    *(uint2*)(pl + 512 + tid * 2) = l;
}

// ================= GEMM2: out = P @ enc, CTA 128x128, k-chunk 32, 2 CTAs/SM =================
#define G2_PW   (128 * RS3)                // 2560 words per P matrix (16 pairs/row)
#define G2_EW   (32 * RS2)                 // 2176 words per E matrix
#define G2_STGW (2 * G2_PW + 2 * G2_EW)    // 9472 words
#define G2_SMEM (2 * G2_STGW * 4)          // 75,776 B -> 2 CTAs/SM

__global__ void __launch_bounds__(256, 2)
gemm2_kernel(float* __restrict__ out) {
    extern __shared__ uint32_t sm[];
    const uint32_t sb = smem_u32(sm);
    const int tid = threadIdx.x, lane = tid & 31, wid = tid >> 5;
    const int l16 = lane & 15, lhi = lane >> 4;
    const int g = lane >> 2, t = lane & 3;
    const int wm = wid >> 1, wd = wid & 1;          // warp tile 32m x 64d
    const int d0 = blockIdx.x * 128, m0 = blockIdx.y * 128, bz = blockIdx.z;

    const uint32_t* Ph = g_ph + ((size_t)bz * SEQ + m0) * 1024;
    const uint32_t* Pl = g_pl + ((size_t)bz * SEQ + m0) * 1024;
    const uint32_t* Eh = g_eh + (size_t)bz * SEQ * 256 + d0 / 2;
    const uint32_t* El = g_el + (size_t)bz * SEQ * 256 + d0 / 2;
    float* Ob = out + ((size_t)bz * SEQ + m0) * DIM + d0;

    float4 acc[2][8];
#pragma unroll
    for (int a = 0; a < 2; a++)
#pragma unroll
        for (int b = 0; b < 8; b++) acc[a][b] = make_float4(0.f, 0.f, 0.f, 0.f);

    // chunk c covers k = c*32 .. c*32+31 (16 pairs)
    auto load2 = [&](int c, uint32_t stg) {
#pragma unroll
        for (int i = 0; i < 2; i++) {                 // P: 128 rows x 4 uint4
            int idx = tid + i * 256;
            int r = idx >> 2, u = idx & 3;
            uint32_t sa = stg + (uint32_t)(r * RS3 + u * 4) * 4;
            cpa16(sa, Ph + (size_t)r * 1024 + c * 16 + u * 4);
            cpa16(sa + G2_PW * 4, Pl + (size_t)r * 1024 + c * 16 + u * 4);
        }
#pragma unroll
        for (int i = 0; i < 2; i++) {                 // E: 32 rows x 16 uint4
            int idx = tid + i * 256;
            int r = idx >> 4, u = idx & 15;
            uint32_t sa = stg + (uint32_t)(2 * G2_PW + r * RS2 + u * 4) * 4;
            cpa16(sa, Eh + (size_t)(c * 32 + r) * 256 + u * 4);
            cpa16(sa + G2_EW * 4, El + (size_t)(c * 32 + r) * 256 + u * 4);
        }
        cpa_commit();
    };

    load2(0, sb);
    cpa_wait0();
    __syncthreads();

    for (int c = 0; c < 64; c++) {
        const int s = c & 1;
        if (c < 63) load2(c + 1, sb + (uint32_t)(s ^ 1) * (G2_STGW * 4));

        const uint32_t base = sb + (uint32_t)s * (G2_STGW * 4);
        const uint32_t aP  = base + (uint32_t)(wm * 32 + l16) * 80 + lhi * 16;
        const uint32_t aPl = aP + G2_PW * 4;
        const uint32_t aE  = base + 2u * G2_PW * 4 + (uint32_t)l16 * 272 + wd * 128 + lhi * 16;
        const uint32_t aEl = aE + G2_EW * 4;
#pragma unroll
        for (int st = 0; st < 2; st++) {
            uint32_t ph[2][4], pl2[2][4];
#pragma unroll
            for (int mt = 0; mt < 2; mt++) {
                ldsm4(ph[mt][0], ph[mt][1], ph[mt][2], ph[mt][3], aP + mt * 1280 + st * 32);
                ldsm4(pl2[mt][0], pl2[mt][1], pl2[mt][2], pl2[mt][3], aPl + mt * 1280 + st * 32);
            }
            uint32_t eh[16], el[16];
#pragma unroll
            for (int q = 0; q < 4; q++) {
                ldsm4t(eh[q * 4], eh[q * 4 + 1], eh[q * 4 + 2], eh[q * 4 + 3],
                       aE + st * (16 * 272) + q * 32);
                ldsm4t(el[q * 4], el[q * 4 + 1], el[q * 4 + 2], el[q * 4 + 3],
                       aEl + st * (16 * 272) + q * 32);
            }
#pragma unroll
            for (int mt = 0; mt < 2; mt++)
#pragma unroll
                for (int np = 0; np < 8; np++) {
                    mma16(acc[mt][np], ph[mt][0], ph[mt][1], ph[mt][2], ph[mt][3],
                          el[np * 2], el[np * 2 + 1]);
                    mma16(acc[mt][np], pl2[mt][0], pl2[mt][1], pl2[mt][2], pl2[mt][3],
                          eh[np * 2], eh[np * 2 + 1]);
                    mma16(acc[mt][np], ph[mt][0], ph[mt][1], ph[mt][2], ph[mt][3],
                          eh[np * 2], eh[np * 2 + 1]);
                }
        }
        cpa_wait0();
        __syncthreads();
    }

#pragma unroll
    for (int mt = 0; mt < 2; mt++) {
        int r = wm * 32 + mt * 16 + g;
#pragma unroll
        for (int np = 0; np < 8; np++) {
            int cc = wd * 64 + np * 8 + (t << 1);
            *(float2*)(Ob + (size_t)r * DIM + cc)       = make_float2(acc[mt][np].x, acc[mt][np].y);
            *(float2*)(Ob + (size_t)(r + 8) * DIM + cc) = make_float2(acc[mt][np].z, acc[mt][np].w);
        }
    }
}

// ================= launch =================
extern "C" void kernel_launch(void* const* d_in, const int* in_sizes, int n_in,
                              void* d_out, int out_size) {
    const float* enc = (const float*)d_in[0];   // enc_outputs [8,2048,512]
    const float* dec = (const float*)d_in[1];   // dec_outputs [8,2048,512]
    float* out = (float*)d_out;                 // [8,2048,512]

    float* S = nullptr;
    cudaGetSymbolAddress((void**)&S, g_S);

    cudaFuncSetAttribute(gemm1_kernel, cudaFuncAttributeMaxDynamicSharedMemorySize, G1_SMEM);
    cudaFuncSetAttribute(gemm2_kernel, cudaFuncAttributeMaxDynamicSharedMemorySize, G2_SMEM);

    split_kernel<<<dim3(4096, 2), 256>>>(enc, dec);
    gemm1_kernel<<<dim3(16, 8, NB), 256, G1_SMEM>>>(S);
    softmax_kernel<<<NB * SEQ, 256>>>();
    gemm2_kernel<<<dim3(4, 16, NB), 256, G2_SMEM>>>(out);
}

// round 16
// speedup vs baseline: 1.4584x; 1.0008x over previous
#include <cuda_runtime.h>
#include <cuda_bf16.h>
#include <cstdint>

#define SEQ 2048
#define DIM 512
#define NB  8

// device scratch: S fp32 + pair-packed split-bf16 operands
__device__ float    g_S [(size_t)NB * SEQ * SEQ];
__device__ uint32_t g_eh[(size_t)NB * SEQ * (DIM / 2)];
__device__ uint32_t g_el[(size_t)NB * SEQ * (DIM / 2)];
__device__ uint32_t g_dh[(size_t)NB * SEQ * (DIM / 2)];
__device__ uint32_t g_dl[(size_t)NB * SEQ * (DIM / 2)];
__device__ uint32_t g_ph[(size_t)NB * SEQ * (SEQ / 2)];
__device__ uint32_t g_pl[(size_t)NB * SEQ * (SEQ / 2)];

// ---------------- helpers ----------------
__device__ __forceinline__ uint32_t smem_u32(const void* p) {
    uint32_t a;
    asm("{ .reg .u64 t; cvta.to.shared.u64 t, %1; cvt.u32.u64 %0, t; }" : "=r"(a) : "l"(p));
    return a;
}

__device__ __forceinline__ void cvt2(float x, float y, uint32_t& hip, uint32_t& lop) {
    __nv_bfloat16 bx = __float2bfloat16_rn(x);
    __nv_bfloat16 by = __float2bfloat16_rn(y);
    float rx = x - __bfloat162float(bx);
    float ry = y - __bfloat162float(by);
    __nv_bfloat162 h; h.x = bx; h.y = by;
    __nv_bfloat162 l; l.x = __float2bfloat16_rn(rx); l.y = __float2bfloat16_rn(ry);
    hip = *reinterpret_cast<uint32_t*>(&h);
    lop = *reinterpret_cast<uint32_t*>(&l);
}

__device__ __forceinline__ void mma16(float4& d,
                                      uint32_t a0, uint32_t a1, uint32_t a2, uint32_t a3,
                                      uint32_t b0, uint32_t b1) {
    asm volatile(
        "mma.sync.aligned.m16n8k16.row.col.f32.bf16.bf16.f32 "
        "{%0,%1,%2,%3},{%4,%5,%6,%7},{%8,%9},{%0,%1,%2,%3};"
        : "+f"(d.x), "+f"(d.y), "+f"(d.z), "+f"(d.w)
        : "r"(a0), "r"(a1), "r"(a2), "r"(a3), "r"(b0), "r"(b1));
}

__device__ __forceinline__ void ldsm4(uint32_t& r0, uint32_t& r1, uint32_t& r2, uint32_t& r3,
                                      uint32_t a) {
    asm volatile("ldmatrix.sync.aligned.m8n8.x4.shared.b16 {%0,%1,%2,%3}, [%4];"
                 : "=r"(r0), "=r"(r1), "=r"(r2), "=r"(r3) : "r"(a));
}
__device__ __forceinline__ void ldsm4t(uint32_t& r0, uint32_t& r1, uint32_t& r2, uint32_t& r3,
                                       uint32_t a) {
    asm volatile("ldmatrix.sync.aligned.m8n8.x4.trans.shared.b16 {%0,%1,%2,%3}, [%4];"
                 : "=r"(r0), "=r"(r1), "=r"(r2), "=r"(r3) : "r"(a));
}

__device__ __forceinline__ void cpa16(uint32_t saddr, const void* g) {
    asm volatile("cp.async.cg.shared.global [%0], [%1], 16;" :: "r"(saddr), "l"(g));
}
__device__ __forceinline__ void cpa_commit() {
    asm volatile("cp.async.commit_group;" ::: "memory");
}
__device__ __forceinline__ void cpa_wait0() {
    asm volatile("cp.async.wait_group 0;" ::: "memory");
}
__device__ __forceinline__ void cpa_wait1() {
    asm volatile("cp.async.wait_group 1;" ::: "memory");
}

#define RS  36   // words per 32-pair row (144 B)
#define RS2 68   // words per 64-pair row (272 B)
#define RS3 20   // words per 16-pair row (80 B)

// ================= split kernel =================
__global__ void __launch_bounds__(256)
split_kernel(const float* __restrict__ enc, const float* __restrict__ dec) {
    const size_t t = (size_t)blockIdx.x * 256 + threadIdx.x;
    const float* src = blockIdx.y ? dec : enc;
    uint32_t* dh = blockIdx.y ? g_dh : g_eh;
    uint32_t* dl = blockIdx.y ? g_dl : g_el;
    float4 v0 = *(const float4*)(src + t * 8);
    float4 v1 = *(const float4*)(src + t * 8 + 4);
    uint4 h, l;
    cvt2(v0.x, v0.y, h.x, l.x);
    cvt2(v0.z, v0.w, h.y, l.y);
    cvt2(v1.x, v1.y, h.z, l.z);
    cvt2(v1.z, v1.w, h.w, l.w);
    *(uint4*)(dh + t * 4) = h;
    *(uint4*)(dl + t * 4) = l;
}

// ================= GEMM1: S = dec @ enc^T, CTA 256x128, cp.async staging =================
#define G1_AW   (256 * RS)
#define G1_BW   (128 * RS)
#define G1_STGW (2 * G1_AW + 2 * G1_BW)
#define G1_SMEM (2 * G1_STGW * 4)   // 221,184 B

__global__ void __launch_bounds__(256)
gemm1_kernel(float* __restrict__ S) {
    extern __shared__ uint32_t sm[];
    const uint32_t sb = smem_u32(sm);
    const int tid = threadIdx.x, lane = tid & 31, wid = tid >> 5;
    const int l16 = lane & 15, lhi = lane >> 4, l8 = lane & 7, mi = lane >> 3;
    const int g = lane >> 2, t = lane & 3;
    const int wm = wid >> 1, wn = wid & 1;
    const int n0 = blockIdx.x * 128, m0 = blockIdx.y * 256, bz = blockIdx.z;

    const uint32_t* Ah = g_dh + ((size_t)bz * SEQ + m0) * 256;
    const uint32_t* Al = g_dl + ((size_t)bz * SEQ + m0) * 256;
    const uint32_t* Bh = g_eh + ((size_t)bz * SEQ + n0) * 256;
    const uint32_t* Bl = g_el + ((size_t)bz * SEQ + n0) * 256;
    float* Cb = S + (size_t)bz * SEQ * SEQ + (size_t)m0 * SEQ + n0;

    float4 acc[4][8];
#pragma unroll
    for (int a = 0; a < 4; a++)
#pragma unroll
        for (int b = 0; b < 8; b++) acc[a][b] = make_float4(0.f, 0.f, 0.f, 0.f);

    auto load1 = [&](int c, uint32_t stg) {
        const int co = c * 32;
#pragma unroll
        for (int i = 0; i < 8; i++) {
            int idx = tid + i * 256;
            int r = idx >> 3, u = idx & 7;
            uint32_t sa = stg + (uint32_t)(r * RS + u * 4) * 4;
            cpa16(sa, Ah + (size_t)r * 256 + co + u * 4);
            cpa16(sa + G1_AW * 4, Al + (size_t)r * 256 + co + u * 4);
        }
#pragma unroll
        for (int i = 0; i < 4; i++) {
            int idx = tid + i * 256;
            int r = idx >> 3, u = idx & 7;
            uint32_t sa = stg + (uint32_t)(2 * G1_AW + r * RS + u * 4) * 4;
            cpa16(sa, Bh + (size_t)r * 256 + co + u * 4);
            cpa16(sa + G1_BW * 4, Bl + (size_t)r * 256 + co + u * 4);
        }
        cpa_commit();
    };

    load1(0, sb);
    cpa_wait0();
    __syncthreads();

    for (int c = 0; c < 8; c++) {
        const int s = c & 1;
        if (c < 7) load1(c + 1, sb + (uint32_t)(s ^ 1) * (G1_STGW * 4));

        const uint32_t base = sb + (uint32_t)s * (G1_STGW * 4);
        const uint32_t aA  = base + (uint32_t)(wm * 64 + l16) * 144 + lhi * 16;
        const uint32_t aAl = aA + G1_AW * 4;
        const uint32_t aB  = base + 2u * G1_AW * 4 +
                             (uint32_t)(wn * 64 + (mi >> 1) * 8 + l8) * 144 + (mi & 1) * 16;
        const uint32_t aBl = aB + G1_BW * 4;
#pragma unroll
        for (int st = 0; st < 4; st++) {
            uint32_t ah[4][4], al[4][4];
#pragma unroll
            for (int mt = 0; mt < 4; mt++) {
                ldsm4(ah[mt][0], ah[mt][1], ah[mt][2], ah[mt][3], aA + mt * 2304 + st * 32);
                ldsm4(al[mt][0], al[mt][1], al[mt][2], al[mt][3], aAl + mt * 2304 + st * 32);
            }
            uint32_t bh[16], bl[16];
#pragma unroll
            for (int q = 0; q < 4; q++) {
                ldsm4(bh[q * 4], bh[q * 4 + 1], bh[q * 4 + 2], bh[q * 4 + 3],
                      aB + q * 16 * 144 + st * 32);
                ldsm4(bl[q * 4], bl[q * 4 + 1], bl[q * 4 + 2], bl[q * 4 + 3],
                      aBl + q * 16 * 144 + st * 32);
            }
#pragma unroll
            for (int mt = 0; mt < 4; mt++)
#pragma unroll
                for (int np = 0; np < 8; np++) {
                    mma16(acc[mt][np], ah[mt][0], ah[mt][1], ah[mt][2], ah[mt][3],
                          bl[np * 2], bl[np * 2 + 1]);
                    mma16(acc[mt][np], al[mt][0], al[mt][1], al[mt][2], al[mt][3],
                          bh[np * 2], bh[np * 2 + 1]);
                    mma16(acc[mt][np], ah[mt][0], ah[mt][1], ah[mt][2], ah[mt][3],
                          bh[np * 2], bh[np * 2 + 1]);
                }
        }
        cpa_wait0();
        __syncthreads();
    }

#pragma unroll
    for (int mt = 0; mt < 4; mt++) {
        int r = wm * 64 + mt * 16 + g;
#pragma unroll
        for (int np = 0; np < 8; np++) {
            int cc = wn * 64 + np * 8 + (t << 1);
            *(float2*)(Cb + (size_t)r * SEQ + cc)       = make_float2(acc[mt][np].x, acc[mt][np].y);
            *(float2*)(Cb + (size_t)(r + 8) * SEQ + cc) = make_float2(acc[mt][np].z, acc[mt][np].w);
        }
    }
}

// ================= softmax: S row -> pair-packed split-bf16 P =================
__global__ void __launch_bounds__(256)
softmax_kernel() {
    const float* p = g_S + (size_t)blockIdx.x * SEQ;
    uint32_t* ph = g_ph + (size_t)blockIdx.x * (SEQ / 2);
    uint32_t* pl = g_pl + (size_t)blockIdx.x * (SEQ / 2);
    __shared__ float red[8];
    const int tid = threadIdx.x, wid = tid >> 5, lane = tid & 31;

    float4 v0 = *(const float4*)(p + tid * 4);
    float4 v1 = *(const float4*)(p + 1024 + tid * 4);

    float m = fmaxf(fmaxf(fmaxf(v0.x, v0.y), fmaxf(v0.z, v0.w)),
                    fmaxf(fmaxf(v1.x, v1.y), fmaxf(v1.z, v1.w)));
#pragma unroll
    for (int o = 16; o; o >>= 1) m = fmaxf(m, __shfl_xor_sync(0xffffffffu, m, o));
    if (!lane) red[wid] = m;
    __syncthreads();
    if (tid < 32) {
        float x = (lane < 8) ? red[lane] : -1e30f;
#pragma unroll
        for (int o = 4; o; o >>= 1) x = fmaxf(x, __shfl_xor_sync(0xffffffffu, x, o));
        if (!lane) red[0] = x;
    }
    __syncthreads();
    float M = red[0];
    __syncthreads();

    v0.x = __expf(v0.x - M); v0.y = __expf(v0.y - M);
    v0.z = __expf(v0.z - M); v0.w = __expf(v0.w - M);
    v1.x = __expf(v1.x - M); v1.y = __expf(v1.y - M);
    v1.z = __expf(v1.z - M); v1.w = __expf(v1.w - M);

    float su = (v0.x + v0.y) + (v0.z + v0.w) + (v1.x + v1.y) + (v1.z + v1.w);
#pragma unroll
    for (int o = 16; o; o >>= 1) su += __shfl_xor_sync(0xffffffffu, su, o);
    if (!lane) red[wid] = su;
    __syncthreads();
    if (tid < 32) {
        float x = (lane < 8) ? red[lane] : 0.0f;
#pragma unroll
        for (int o = 4; o; o >>= 1) x += __shfl_xor_sync(0xffffffffu, x, o);
        if (!lane) red[0] = x;
    }
    __syncthreads();
    float inv = 1.0f / red[0];

    v0.x *= inv; v0.y *= inv; v0.z *= inv; v0.w *= inv;
    v1.x *= inv; v1.y *= inv; v1.z *= inv; v1.w *= inv;

    uint2 h, l;
    cvt2(v0.x, v0.y, h.x, l.x);
    cvt2(v0.z, v0.w, h.y, l.y);
    *(uint2*)(ph + tid * 2) = h;
    *(uint2*)(pl + tid * 2) = l;
    cvt2(v1.x, v1.y, h.x, l.x);
    cvt2(v1.z, v1.w, h.y, l.y);
    *(uint2*)(ph + 512 + tid * 2) = h;
    *(uint2*)(pl + 512 + tid * 2) = l;
}

// ================= GEMM2: out = P @ enc, CTA 128x128, k-chunk 32, 3-stage, 2 CTAs/SM ======
#define G2_PW   (128 * RS3)                // 2560 words per P matrix
#define G2_EW   (32 * RS2)                 // 2176 words per E matrix
#define G2_STGW (2 * G2_PW + 2 * G2_EW)    // 9472 words = 37,888 B
#define G2_SMEM (3 * G2_STGW * 4)          // 113,664 B -> 2 CTAs/SM

__global__ void __launch_bounds__(256, 2)
gemm2_kernel(float* __restrict__ out) {
    extern __shared__ uint32_t sm[];
    const uint32_t sb = smem_u32(sm);
    const int tid = threadIdx.x, lane = tid & 31, wid = tid >> 5;
    const int l16 = lane & 15, lhi = lane >> 4;
    const int g = lane >> 2, t = lane & 3;
    const int wm = wid >> 1, wd = wid & 1;          // warp tile 32m x 64d
    const int d0 = blockIdx.x * 128, m0 = blockIdx.y * 128, bz = blockIdx.z;

    const uint32_t* Ph = g_ph + ((size_t)bz * SEQ + m0) * 1024;
    const uint32_t* Pl = g_pl + ((size_t)bz * SEQ + m0) * 1024;
    const uint32_t* Eh = g_eh + (size_t)bz * SEQ * 256 + d0 / 2;
    const uint32_t* El = g_el + (size_t)bz * SEQ * 256 + d0 / 2;
    float* Ob = out + ((size_t)bz * SEQ + m0) * DIM + d0;

    float4 acc[2][8];
#pragma unroll
    for (int a = 0; a < 2; a++)
#pragma unroll
        for (int b = 0; b < 8; b++) acc[a][b] = make_float4(0.f, 0.f, 0.f, 0.f);

    // chunk c covers k = c*32 .. c*32+31 (16 pairs)
    auto load2 = [&](int c, uint32_t stg) {
#pragma unroll
        for (int i = 0; i < 2; i++) {                 // P: 128 rows x 4 uint4
            int idx = tid + i * 256;
            int r = idx >> 2, u = idx & 3;
            uint32_t sa = stg + (uint32_t)(r * RS3 + u * 4) * 4;
            cpa16(sa, Ph + (size_t)r * 1024 + c * 16 + u * 4);
            cpa16(sa + G2_PW * 4, Pl + (size_t)r * 1024 + c * 16 + u * 4);
        }
#pragma unroll
        for (int i = 0; i < 2; i++) {                 // E: 32 rows x 16 uint4
            int idx = tid + i * 256;
            int r = idx >> 4, u = idx & 15;
            uint32_t sa = stg + (uint32_t)(2 * G2_PW + r * RS2 + u * 4) * 4;
            cpa16(sa, Eh + (size_t)(c * 32 + r) * 256 + u * 4);
            cpa16(sa + G2_EW * 4, El + (size_t)(c * 32 + r) * 256 + u * 4);
        }
        cpa_commit();
    };

    // prologue: preload chunks 0 and 1 into stages 0, 1
    load2(0, sb);
    load2(1, sb + (uint32_t)(G2_STGW * 4));

    for (int c = 0; c < 64; c++) {
        // wait for chunk c's load (all groups except the newest one)
        if (c < 63) cpa_wait1(); else cpa_wait0();
        __syncthreads();
        // prefetch chunk c+2 into stage (c+2)%3 (last read by mma(c-1), done pre-barrier)
        if (c + 2 < 64) load2(c + 2, sb + (uint32_t)((c + 2) % 3) * (G2_STGW * 4));

        const uint32_t base = sb + (uint32_t)(c % 3) * (G2_STGW * 4);
        const uint32_t aP  = base + (uint32_t)(wm * 32 + l16) * 80 + lhi * 16;
        const uint32_t aPl = aP + G2_PW * 4;
        const uint32_t aE  = base + 2u * G2_PW * 4 + (uint32_t)l16 * 272 + wd * 128 + lhi * 16;
        const uint32_t aEl = aE + G2_EW * 4;
#pragma unroll
        for (int st = 0; st < 2; st++) {
            uint32_t ph[2][4], pl2[2][4];
#pragma unroll
            for (int mt = 0; mt < 2; mt++) {
                ldsm4(ph[mt][0], ph[mt][1], ph[mt][2], ph[mt][3], aP + mt * 1280 + st * 32);
                ldsm4(pl2[mt][0], pl2[mt][1], pl2[mt][2], pl2[mt][3], aPl + mt * 1280 + st * 32);
            }
            uint32_t eh[16], el[16];
#pragma unroll
            for (int q = 0; q < 4; q++) {
                ldsm4t(eh[q * 4], eh[q * 4 + 1], eh[q * 4 + 2], eh[q * 4 + 3],
                       aE + st * (16 * 272) + q * 32);
                ldsm4t(el[q * 4], el[q * 4 + 1], el[q * 4 + 2], el[q * 4 + 3],
                       aEl + st * (16 * 272) + q * 32);
            }
#pragma unroll
            for (int mt = 0; mt < 2; mt++)
#pragma unroll
                for (int np = 0; np < 8; np++) {
                    mma16(acc[mt][np], ph[mt][0], ph[mt][1], ph[mt][2], ph[mt][3],
                          el[np * 2], el[np * 2 + 1]);
                    mma16(acc[mt][np], pl2[mt][0], pl2[mt][1], pl2[mt][2], pl2[mt][3],
                          eh[np * 2], eh[np * 2 + 1]);
                    mma16(acc[mt][np], ph[mt][0], ph[mt][1], ph[mt][2], ph[mt][3],
                          eh[np * 2], eh[np * 2 + 1]);
                }
        }
    }

#pragma unroll
    for (int mt = 0; mt < 2; mt++) {
        int r = wm * 32 + mt * 16 + g;
#pragma unroll
        for (int np = 0; np < 8; np++) {
            int cc = wd * 64 + np * 8 + (t << 1);
            *(float2*)(Ob + (size_t)r * DIM + cc)       = make_float2(acc[mt][np].x, acc[mt][np].y);
            *(float2*)(Ob + (size_t)(r + 8) * DIM + cc) = make_float2(acc[mt][np].z, acc[mt][np].w);
        }
    }
}

// ================= launch =================
extern "C" void kernel_launch(void* const* d_in, const int* in_sizes, int n_in,
                              void* d_out, int out_size) {
    const float* enc = (const float*)d_in[0];   // enc_outputs [8,2048,512]
    const float* dec = (const float*)d_in[1];   // dec_outputs [8,2048,512]
    float* out = (float*)d_out;                 // [8,2048,512]

    float* S = nullptr;
    cudaGetSymbolAddress((void**)&S, g_S);

    cudaFuncSetAttribute(gemm1_kernel, cudaFuncAttributeMaxDynamicSharedMemorySize, G1_SMEM);
    cudaFuncSetAttribute(gemm2_kernel, cudaFuncAttributeMaxDynamicSharedMemorySize, G2_SMEM);

    split_kernel<<<dim3(4096, 2), 256>>>(enc, dec);
    gemm1_kernel<<<dim3(16, 8, NB), 256, G1_SMEM>>>(S);
    softmax_kernel<<<NB * SEQ, 256>>>();
    gemm2_kernel<<<dim3(4, 16, NB), 256, G2_SMEM>>>(out);
}